// round 1
// baseline (speedup 1.0000x reference)
#include <cuda_runtime.h>
#include <math.h>

#define BB   16
#define NN   4096
#define DD   256
#define NSL  8
#define NPI  4
#define HH   256
#define SCALE_F 0.0625f
#define EPS_F   1e-8f

// ---------------- scratch (device globals; no allocation allowed) ----------------
__device__ float g_x[BB*NN*DD];
__device__ float g_k[BB*NN*DD];
__device__ float g_v[BB*NN*DD];

__device__ float g_sem_slots[BB*NSL*DD];
__device__ float g_sem_q[BB*NSL*DD];
__device__ float g_sem_dots[BB*NSL*NN];
__device__ float g_sem_attn[BB*NSL*NN];
__device__ float g_sem_rowsum[BB*NSL];
__device__ float g_sem_acc[BB*NSL*DD];
__device__ float g_sem_w[BB*NSL*NN];

__device__ float g_inst_slots[BB*NSL*NPI*DD];
__device__ float g_inst_q[BB*NSL*NPI*DD];
__device__ float g_inst_dots[BB*NSL*NPI*NN];
__device__ float g_inst_attn[BB*NSL*NPI*NN];
__device__ float g_inst_rowsum[BB*NSL*NPI];
__device__ float g_inst_acc[BB*NSL*NPI*DD];

// ---------------- helpers ----------------
__device__ __forceinline__ float warp_sum(float v) {
#pragma unroll
    for (int o = 16; o; o >>= 1) v += __shfl_xor_sync(0xffffffffu, v, o);
    return v;
}

// block-wide mean/inv-std over 256 values (one per thread). Leaves rs/rs2 reusable.
__device__ __forceinline__ void block_stats(float v, float* rs, float* rs2, int t,
                                            float& m, float& inv) {
    float s  = warp_sum(v);
    float s2 = warp_sum(v * v);
    if ((t & 31) == 0) { rs[t >> 5] = s; rs2[t >> 5] = s2; }
    __syncthreads();
    float sum = 0.f, sum2 = 0.f;
#pragma unroll
    for (int i = 0; i < 8; i++) { sum += rs[i]; sum2 += rs2[i]; }
    m = sum * (1.0f / 256.0f);
    float var = sum2 * (1.0f / 256.0f) - m * m;
    inv = rsqrtf(var + 1e-5f);
    __syncthreads();
}

// ---------------- 1) LN over inputs ----------------
__global__ void __launch_bounds__(256) ln_input_kernel(const float* __restrict__ x,
                                                       const float* __restrict__ g,
                                                       const float* __restrict__ b) {
    __shared__ float rs[8], rs2[8];
    int row = blockIdx.x;
    int t   = threadIdx.x;
    float v = x[(size_t)row * DD + t];
    float m, inv;
    block_stats(v, rs, rs2, t, m, inv);
    g_x[(size_t)row * DD + t] = (v - m) * inv * g[t] + b[t];
}

// ---------------- 2) SGEMM: C[M,256] = g_x[M,256] @ W[256,256] + bias ----------------
// BM=128, BN=128, BK=16, 256 threads, 8x8 per thread.
__global__ void __launch_bounds__(256) sgemm_kernel(const float* __restrict__ W,
                                                    const float* __restrict__ bias,
                                                    int which) {
    const float* A = g_x;
    float* C = which ? g_v : g_k;

    __shared__ float As[16][128];
    __shared__ float Bs[16][132];   // padded; rows stay 16B aligned (132*4=528)

    int t  = threadIdx.x;
    int bm = blockIdx.y, bn = blockIdx.x;
    int tx = t & 15, ty = t >> 4;

    float acc[8][8];
#pragma unroll
    for (int i = 0; i < 8; i++)
#pragma unroll
        for (int j = 0; j < 8; j++) acc[i][j] = 0.f;

    int arow = t >> 1;
    int acol = (t & 1) * 8;
    int brow = t >> 4;
    int bcol = (t & 15) * 8;

    const float* Aptr = A + ((size_t)bm * 128 + arow) * 256 + acol;
    const float* Wptr = W + (size_t)brow * 256 + bn * 128 + bcol;

    for (int k0 = 0; k0 < 256; k0 += 16) {
        float4 a0 = *(const float4*)(Aptr + k0);
        float4 a1 = *(const float4*)(Aptr + k0 + 4);
        float4 b0 = *(const float4*)(Wptr + (size_t)k0 * 256);
        float4 b1 = *(const float4*)(Wptr + (size_t)k0 * 256 + 4);

        As[acol + 0][arow] = a0.x; As[acol + 1][arow] = a0.y;
        As[acol + 2][arow] = a0.z; As[acol + 3][arow] = a0.w;
        As[acol + 4][arow] = a1.x; As[acol + 5][arow] = a1.y;
        As[acol + 6][arow] = a1.z; As[acol + 7][arow] = a1.w;
        *(float4*)&Bs[brow][bcol]     = b0;
        *(float4*)&Bs[brow][bcol + 4] = b1;
        __syncthreads();

#pragma unroll
        for (int kk = 0; kk < 16; kk++) {
            float a[8], b[8];
            *(float4*)(a)     = *(const float4*)&As[kk][ty * 8];
            *(float4*)(a + 4) = *(const float4*)&As[kk][ty * 8 + 4];
            *(float4*)(b)     = *(const float4*)&Bs[kk][tx * 8];
            *(float4*)(b + 4) = *(const float4*)&Bs[kk][tx * 8 + 4];
#pragma unroll
            for (int i = 0; i < 8; i++)
#pragma unroll
                for (int j = 0; j < 8; j++) acc[i][j] += a[i] * b[j];
        }
        __syncthreads();
    }

    float bi[8];
#pragma unroll
    for (int j = 0; j < 8; j++) bi[j] = bias[bn * 128 + tx * 8 + j];

#pragma unroll
    for (int i = 0; i < 8; i++) {
        size_t row = (size_t)bm * 128 + ty * 8 + i;
        float4 o0 = make_float4(acc[i][0] + bi[0], acc[i][1] + bi[1],
                                acc[i][2] + bi[2], acc[i][3] + bi[3]);
        float4 o1 = make_float4(acc[i][4] + bi[4], acc[i][5] + bi[5],
                                acc[i][6] + bi[6], acc[i][7] + bi[7]);
        *(float4*)(C + row * 256 + bn * 128 + tx * 8)     = o0;
        *(float4*)(C + row * 256 + bn * 128 + tx * 8 + 4) = o1;
    }
}

// ---------------- 3) init kernels ----------------
__global__ void sem_init_kernel(const float* __restrict__ mu) {
    int r = blockIdx.x;               // 0..B*NS-1
    int i = r & 7;
    g_sem_slots[(size_t)r * DD + threadIdx.x] = mu[i * DD + threadIdx.x];
}

__global__ void inst_init_kernel(const float* __restrict__ mu,
                                 const float* __restrict__ sigma,
                                 const float* __restrict__ noise) {
    size_t idx = (size_t)blockIdx.x * 256 + threadIdx.x;  // < B*NS*NP*D
    int d = idx & 255;
    int s = (idx >> 10) & 7;
    g_inst_slots[idx] = mu[s * DD + d] + expf(sigma[s * DD + d]) * noise[idx];
}

__global__ void zero_sem_kernel() {
    int idx = blockIdx.x * 256 + threadIdx.x;   // grid 128 -> 32768
    g_sem_acc[idx] = 0.f;
    if (idx < BB * NSL) g_sem_rowsum[idx] = 0.f;
}

__global__ void zero_inst_kernel() {
    int idx = blockIdx.x * 256 + threadIdx.x;   // grid 512 -> 131072
    g_inst_acc[idx] = 0.f;
    if (idx < BB * NSL * NPI) g_inst_rowsum[idx] = 0.f;
}

// ---------------- 4) q projection: q = LN(slots) @ Wq + bq (4 rows / block) ----------------
__device__ __forceinline__ void slot_q_impl(const float* __restrict__ slots,
                                            float* __restrict__ q,
                                            const float* __restrict__ lng,
                                            const float* __restrict__ lnb,
                                            const float* __restrict__ Wq,
                                            const float* __restrict__ bq) {
    __shared__ float sln[4][DD];
    __shared__ float rs[8], rs2[8];
    int t  = threadIdx.x;
    int r0 = blockIdx.x * 4;
    float gg = lng[t], bb = lnb[t];

#pragma unroll
    for (int r = 0; r < 4; r++) {
        float v = slots[(size_t)(r0 + r) * DD + t];
        float m, inv;
        block_stats(v, rs, rs2, t, m, inv);
        sln[r][t] = (v - m) * inv * gg + bb;
    }
    __syncthreads();

    float a0 = 0.f, a1 = 0.f, a2 = 0.f, a3 = 0.f;
#pragma unroll 4
    for (int d = 0; d < DD; d++) {
        float wv = Wq[d * DD + t];
        a0 += sln[0][d] * wv;
        a1 += sln[1][d] * wv;
        a2 += sln[2][d] * wv;
        a3 += sln[3][d] * wv;
    }
    float qb = bq[t];
    q[(size_t)(r0 + 0) * DD + t] = a0 + qb;
    q[(size_t)(r0 + 1) * DD + t] = a1 + qb;
    q[(size_t)(r0 + 2) * DD + t] = a2 + qb;
    q[(size_t)(r0 + 3) * DD + t] = a3 + qb;
}

__global__ void __launch_bounds__(256) sem_q_kernel(const float* lng, const float* lnb,
                                                    const float* Wq, const float* bq) {
    slot_q_impl(g_sem_slots, g_sem_q, lng, lnb, Wq, bq);
}
__global__ void __launch_bounds__(256) inst_q_kernel(const float* lng, const float* lnb,
                                                     const float* Wq, const float* bq) {
    slot_q_impl(g_inst_slots, g_inst_q, lng, lnb, Wq, bq);
}

// ---------------- 5) sem dots + softmax(over slots) + eps + rowsum ----------------
__global__ void __launch_bounds__(256) sem_dots_kernel() {
    int b  = blockIdx.y;
    int n0 = blockIdx.x * 256;
    int t  = threadIdx.x;
    int n  = n0 + t;

    __shared__ float qs[NSL][DD];
    for (int idx = t; idx < NSL * DD; idx += 256)
        qs[idx >> 8][idx & 255] = g_sem_q[(size_t)b * NSL * DD + idx];
    __syncthreads();

    float acc[NSL];
#pragma unroll
    for (int i = 0; i < NSL; i++) acc[i] = 0.f;

    const float* kp = g_k + ((size_t)b * NN + n) * DD;
#pragma unroll 1
    for (int d0 = 0; d0 < DD; d0 += 16) {
        float4 k0 = *(const float4*)(kp + d0);
        float4 k1 = *(const float4*)(kp + d0 + 4);
        float4 k2 = *(const float4*)(kp + d0 + 8);
        float4 k3 = *(const float4*)(kp + d0 + 12);
#pragma unroll
        for (int i = 0; i < NSL; i++) {
            float4 q0 = *(const float4*)&qs[i][d0];
            float4 q1 = *(const float4*)&qs[i][d0 + 4];
            float4 q2 = *(const float4*)&qs[i][d0 + 8];
            float4 q3 = *(const float4*)&qs[i][d0 + 12];
            acc[i] += k0.x * q0.x + k0.y * q0.y + k0.z * q0.z + k0.w * q0.w
                    + k1.x * q1.x + k1.y * q1.y + k1.z * q1.z + k1.w * q1.w
                    + k2.x * q2.x + k2.y * q2.y + k2.z * q2.z + k2.w * q2.w
                    + k3.x * q3.x + k3.y * q3.y + k3.z * q3.z + k3.w * q3.w;
        }
    }

    float dv[NSL], e[NSL];
    float mx = -1e30f;
#pragma unroll
    for (int i = 0; i < NSL; i++) { dv[i] = acc[i] * SCALE_F; mx = fmaxf(mx, dv[i]); }
    float ssum = 0.f;
#pragma unroll
    for (int i = 0; i < NSL; i++) { e[i] = expf(dv[i] - mx); ssum += e[i]; }
    float inv = 1.0f / ssum;

    size_t base = (size_t)b * NSL * NN + n;
    int l = t & 31;
#pragma unroll
    for (int i = 0; i < NSL; i++) {
        float at = e[i] * inv + EPS_F;
        g_sem_dots[base + (size_t)i * NN] = dv[i];
        g_sem_attn[base + (size_t)i * NN] = at;
        float sv = warp_sum(at);
        if (l == 0) atomicAdd(&g_sem_rowsum[b * NSL + i], sv);
    }
}

// ---------------- 6) sem update: acc[b,i,d] += sum_n v[b,n,d]*attn[b,i,n] ----------------
__global__ void __launch_bounds__(256) sem_update_kernel() {
    int b  = blockIdx.y;
    int n0 = blockIdx.x * 256;
    int t  = threadIdx.x;

    __shared__ float sat[NSL][256];
    for (int idx = t; idx < NSL * 256; idx += 256) {
        int i = idx >> 8, nn = idx & 255;
        sat[i][nn] = g_sem_attn[(size_t)b * NSL * NN + (size_t)i * NN + n0 + nn];
    }
    __syncthreads();

    float acc[NSL];
#pragma unroll
    for (int i = 0; i < NSL; i++) acc[i] = 0.f;

    const float* vp = g_v + ((size_t)b * NN + n0) * DD + t;
#pragma unroll 1
    for (int nn = 0; nn < 256; nn += 4) {
        float v0 = vp[(size_t)(nn + 0) * DD];
        float v1 = vp[(size_t)(nn + 1) * DD];
        float v2 = vp[(size_t)(nn + 2) * DD];
        float v3 = vp[(size_t)(nn + 3) * DD];
#pragma unroll
        for (int i = 0; i < NSL; i++) {
            float4 a4 = *(const float4*)&sat[i][nn];
            acc[i] += v0 * a4.x + v1 * a4.y + v2 * a4.z + v3 * a4.w;
        }
    }
#pragma unroll
    for (int i = 0; i < NSL; i++)
        atomicAdd(&g_sem_acc[(size_t)(b * NSL + i) * DD + t], acc[i]);
}

// ---------------- 7) slots = s1 + MLP(LN(s1)), s1 = slots + acc/rowsum (4 rows/block) ----------------
__device__ __forceinline__ void slot_mlp_impl(float* __restrict__ slots,
                                              const float* __restrict__ acc,
                                              const float* __restrict__ rowsum,
                                              const float* __restrict__ lng,
                                              const float* __restrict__ lnb,
                                              const float* __restrict__ W1,
                                              const float* __restrict__ b1,
                                              const float* __restrict__ W2,
                                              const float* __restrict__ b2) {
    __shared__ float s1[4][DD];
    __shared__ float sln[4][DD];
    __shared__ float hs[4][HH];
    __shared__ float rs[8], rs2[8];
    int t  = threadIdx.x;
    int r0 = blockIdx.x * 4;
    float gg = lng[t], bb = lnb[t];

#pragma unroll
    for (int r = 0; r < 4; r++) {
        int row = r0 + r;
        float v = slots[(size_t)row * DD + t] + acc[(size_t)row * DD + t] / rowsum[row];
        s1[r][t] = v;
        float m, inv;
        block_stats(v, rs, rs2, t, m, inv);
        sln[r][t] = (v - m) * inv * gg + bb;
    }
    __syncthreads();

    float h0 = 0.f, h1 = 0.f, h2 = 0.f, h3 = 0.f;
#pragma unroll 4
    for (int d = 0; d < DD; d++) {
        float wv = W1[d * HH + t];
        h0 += sln[0][d] * wv;
        h1 += sln[1][d] * wv;
        h2 += sln[2][d] * wv;
        h3 += sln[3][d] * wv;
    }
    float b1v = b1[t];
    hs[0][t] = fmaxf(h0 + b1v, 0.f);
    hs[1][t] = fmaxf(h1 + b1v, 0.f);
    hs[2][t] = fmaxf(h2 + b1v, 0.f);
    hs[3][t] = fmaxf(h3 + b1v, 0.f);
    __syncthreads();

    float o0 = 0.f, o1 = 0.f, o2 = 0.f, o3 = 0.f;
#pragma unroll 4
    for (int j = 0; j < HH; j++) {
        float wv = W2[j * DD + t];
        o0 += hs[0][j] * wv;
        o1 += hs[1][j] * wv;
        o2 += hs[2][j] * wv;
        o3 += hs[3][j] * wv;
    }
    float b2v = b2[t];
    slots[(size_t)(r0 + 0) * DD + t] = s1[0][t] + o0 + b2v;
    slots[(size_t)(r0 + 1) * DD + t] = s1[1][t] + o1 + b2v;
    slots[(size_t)(r0 + 2) * DD + t] = s1[2][t] + o2 + b2v;
    slots[(size_t)(r0 + 3) * DD + t] = s1[3][t] + o3 + b2v;
}

__global__ void __launch_bounds__(256) sem_mlp_kernel(const float* lng, const float* lnb,
                                                      const float* W1, const float* b1,
                                                      const float* W2, const float* b2) {
    slot_mlp_impl(g_sem_slots, g_sem_acc, g_sem_rowsum, lng, lnb, W1, b1, W2, b2);
}
__global__ void __launch_bounds__(256) inst_mlp_kernel(const float* lng, const float* lnb,
                                                       const float* W1, const float* b1,
                                                       const float* W2, const float* b2) {
    slot_mlp_impl(g_inst_slots, g_inst_acc, g_inst_rowsum, lng, lnb, W1, b1, W2, b2);
}

// ---------------- 8) sem_w = softmax over slots of final sem dots ----------------
__global__ void __launch_bounds__(256) sem_w_kernel() {
    int b = blockIdx.y;
    int n = blockIdx.x * 256 + threadIdx.x;
    size_t base = (size_t)b * NSL * NN + n;
    float dv[NSL];
    float mx = -1e30f;
#pragma unroll
    for (int i = 0; i < NSL; i++) { dv[i] = g_sem_dots[base + (size_t)i * NN]; mx = fmaxf(mx, dv[i]); }
    float ssum = 0.f;
#pragma unroll
    for (int i = 0; i < NSL; i++) { dv[i] = expf(dv[i] - mx); ssum += dv[i]; }
    float inv = 1.0f / ssum;
#pragma unroll
    for (int i = 0; i < NSL; i++) g_sem_w[base + (size_t)i * NN] = dv[i] * inv;
}

// ---------------- 9) inst dots + softmax(over NP) * sem_w + rowsum ----------------
__global__ void __launch_bounds__(256) inst_dots_kernel() {
    int b  = blockIdx.y;
    int n0 = blockIdx.x * 256;
    int t  = threadIdx.x;
    int n  = n0 + t;

    __shared__ float qs[NSL * NPI][DD];   // 32 KB
    for (int idx = t; idx < 32 * DD; idx += 256)
        qs[idx >> 8][idx & 255] = g_inst_q[(size_t)b * 32 * DD + idx];
    __syncthreads();

    float acc[32];
#pragma unroll
    for (int i = 0; i < 32; i++) acc[i] = 0.f;

    const float* kp = g_k + ((size_t)b * NN + n) * DD;
#pragma unroll 1
    for (int d0 = 0; d0 < DD; d0 += 16) {
        float4 k0 = *(const float4*)(kp + d0);
        float4 k1 = *(const float4*)(kp + d0 + 4);
        float4 k2 = *(const float4*)(kp + d0 + 8);
        float4 k3 = *(const float4*)(kp + d0 + 12);
#pragma unroll
        for (int i = 0; i < 32; i++) {
            float4 q0 = *(const float4*)&qs[i][d0];
            float4 q1 = *(const float4*)&qs[i][d0 + 4];
            float4 q2 = *(const float4*)&qs[i][d0 + 8];
            float4 q3 = *(const float4*)&qs[i][d0 + 12];
            acc[i] += k0.x * q0.x + k0.y * q0.y + k0.z * q0.z + k0.w * q0.w
                    + k1.x * q1.x + k1.y * q1.y + k1.z * q1.z + k1.w * q1.w
                    + k2.x * q2.x + k2.y * q2.y + k2.z * q2.z + k2.w * q2.w
                    + k3.x * q3.x + k3.y * q3.y + k3.z * q3.z + k3.w * q3.w;
        }
    }

    size_t dbase = (size_t)b * 32 * NN + n;
    int l = t & 31;
#pragma unroll
    for (int s = 0; s < 8; s++) {
        float dv[NPI], e[NPI];
        float mx = -1e30f;
#pragma unroll
        for (int p = 0; p < NPI; p++) { dv[p] = acc[s * 4 + p] * SCALE_F; mx = fmaxf(mx, dv[p]); }
        float ssum = 0.f;
#pragma unroll
        for (int p = 0; p < NPI; p++) { e[p] = expf(dv[p] - mx); ssum += e[p]; }
        float invs = 1.0f / ssum;
        float wv = g_sem_w[(size_t)b * NSL * NN + (size_t)s * NN + n];
#pragma unroll
        for (int p = 0; p < NPI; p++) {
            int sp = s * 4 + p;
            float at = (e[p] * invs + EPS_F) * wv;
            g_inst_dots[dbase + (size_t)sp * NN] = dv[p];
            g_inst_attn[dbase + (size_t)sp * NN] = at;
            float sv = warp_sum(at);
            if (l == 0) atomicAdd(&g_inst_rowsum[b * 32 + sp], sv);
        }
    }
}

// ---------------- 10) inst update ----------------
__global__ void __launch_bounds__(256) inst_update_kernel() {
    int b  = blockIdx.y;
    int n0 = blockIdx.x * 256;
    int t  = threadIdx.x;

    __shared__ float sat[32][256];   // 32 KB
    for (int idx = t; idx < 32 * 256; idx += 256) {
        int i = idx >> 8, nn = idx & 255;
        sat[i][nn] = g_inst_attn[(size_t)b * 32 * NN + (size_t)i * NN + n0 + nn];
    }
    __syncthreads();

    float acc[32];
#pragma unroll
    for (int i = 0; i < 32; i++) acc[i] = 0.f;

    const float* vp = g_v + ((size_t)b * NN + n0) * DD + t;
#pragma unroll 1
    for (int nn = 0; nn < 256; nn += 4) {
        float v0 = vp[(size_t)(nn + 0) * DD];
        float v1 = vp[(size_t)(nn + 1) * DD];
        float v2 = vp[(size_t)(nn + 2) * DD];
        float v3 = vp[(size_t)(nn + 3) * DD];
#pragma unroll
        for (int i = 0; i < 32; i++) {
            float4 a4 = *(const float4*)&sat[i][nn];
            acc[i] += v0 * a4.x + v1 * a4.y + v2 * a4.z + v3 * a4.w;
        }
    }
#pragma unroll
    for (int i = 0; i < 32; i++)
        atomicAdd(&g_inst_acc[(size_t)(b * 32 + i) * DD + t], acc[i]);
}

// ---------------- 11) assemble output ----------------
__global__ void __launch_bounds__(256) write_out_kernel(float* __restrict__ out) {
    size_t idx = (size_t)blockIdx.x * 256 + threadIdx.x;
    const size_t A1 = 32768;       // sem_slots  [16,8,256]
    const size_t A2 = 557056;      // + sem_dots [16,8,4096]
    const size_t A3 = 688128;      // + inst_slots [16,8,4,256]
    const size_t A4 = 2785280;     // + inst_dots  [16,8,4,4096]
    if (idx >= A4) return;
    float v;
    if (idx < A1)      v = g_sem_slots[idx];
    else if (idx < A2) v = g_sem_dots[idx - A1];
    else if (idx < A3) v = g_inst_slots[idx - A2];
    else               v = g_inst_dots[idx - A3];
    out[idx] = v;
}

// ---------------- launch ----------------
extern "C" void kernel_launch(void* const* d_in, const int* in_sizes, int n_in,
                              void* d_out, int out_size) {
    (void)in_sizes; (void)n_in; (void)out_size;
    const float* inputs      = (const float*)d_in[0];
    // d_in[1] = bs (unused), d_in[2] = weight (unused)
    const float* noise       = (const float*)d_in[3];
    const float* ln_in_g     = (const float*)d_in[4];
    const float* ln_in_b     = (const float*)d_in[5];
    const float* ln_s_g      = (const float*)d_in[6];
    const float* ln_s_b      = (const float*)d_in[7];
    const float* ln_ff_g     = (const float*)d_in[8];
    const float* ln_ff_b     = (const float*)d_in[9];
    const float* slots_mu    = (const float*)d_in[10];
    const float* slots_sigma = (const float*)d_in[11];
    const float* Wq          = (const float*)d_in[12];
    const float* bq          = (const float*)d_in[13];
    const float* Wk          = (const float*)d_in[14];
    const float* bk          = (const float*)d_in[15];
    const float* Wv          = (const float*)d_in[16];
    const float* bv          = (const float*)d_in[17];
    const float* W1          = (const float*)d_in[18];
    const float* b1          = (const float*)d_in[19];
    const float* W2          = (const float*)d_in[20];
    const float* b2          = (const float*)d_in[21];
    float* out = (float*)d_out;

    ln_input_kernel<<<BB * NN, 256>>>(inputs, ln_in_g, ln_in_b);

    dim3 gemm_grid(2, 512);
    sgemm_kernel<<<gemm_grid, 256>>>(Wk, bk, 0);
    sgemm_kernel<<<gemm_grid, 256>>>(Wv, bv, 1);

    sem_init_kernel<<<BB * NSL, 256>>>(slots_mu);

    dim3 bn_grid(16, 16);
    for (int it = 0; it < 3; it++) {
        zero_sem_kernel<<<128, 256>>>();
        sem_q_kernel<<<BB * NSL / 4, 256>>>(ln_s_g, ln_s_b, Wq, bq);
        sem_dots_kernel<<<bn_grid, 256>>>();
        sem_update_kernel<<<bn_grid, 256>>>();
        sem_mlp_kernel<<<BB * NSL / 4, 256>>>(ln_ff_g, ln_ff_b, W1, b1, W2, b2);
    }

    sem_w_kernel<<<bn_grid, 256>>>();
    inst_init_kernel<<<BB * NSL * NPI, 256>>>(slots_mu, slots_sigma, noise);

    for (int it = 0; it < 3; it++) {
        zero_inst_kernel<<<512, 256>>>();
        inst_q_kernel<<<BB * NSL * NPI / 4, 256>>>(ln_s_g, ln_s_b, Wq, bq);
        inst_dots_kernel<<<bn_grid, 256>>>();
        inst_update_kernel<<<bn_grid, 256>>>();
        inst_mlp_kernel<<<BB * NSL * NPI / 4, 256>>>(ln_ff_g, ln_ff_b, W1, b1, W2, b2);
    }

    write_out_kernel<<<10880, 256>>>(out);
}

// round 2
// speedup vs baseline: 1.2309x; 1.2309x over previous
#include <cuda_runtime.h>
#include <math.h>
#include <stdint.h>

#define BB   16
#define NN   4096
#define DD   256
#define NSL  8
#define NPI  4
#define HH   256
#define SCALE_F 0.0625f
#define EPS_F   1e-8f

// ---------------- scratch (device globals; no allocation allowed) ----------------
__device__ float g_x[BB*NN*DD];
__device__ float g_k[BB*NN*DD];
__device__ float g_v[BB*NN*DD];

__device__ float g_sem_slots[BB*NSL*DD];
__device__ float g_sem_q[BB*NSL*DD];
__device__ float g_sem_dots[BB*NSL*NN];
__device__ float g_sem_rowsum[BB*NSL];
__device__ float g_sem_acc[BB*NSL*DD];

__device__ float g_inst_slots[BB*NSL*NPI*DD];
__device__ float g_inst_q[BB*NSL*NPI*DD];
__device__ float g_inst_dots[BB*NSL*NPI*NN];
__device__ float g_inst_rowsum[BB*NSL*NPI];
__device__ float g_inst_acc[BB*NSL*NPI*DD];

// ---------------- helpers ----------------
__device__ __forceinline__ float warp_sum(float v) {
#pragma unroll
    for (int o = 16; o; o >>= 1) v += __shfl_xor_sync(0xffffffffu, v, o);
    return v;
}

__device__ __forceinline__ void block_stats(float v, float* rs, float* rs2, int t,
                                            float& m, float& inv) {
    float s  = warp_sum(v);
    float s2 = warp_sum(v * v);
    if ((t & 31) == 0) { rs[t >> 5] = s; rs2[t >> 5] = s2; }
    __syncthreads();
    float sum = 0.f, sum2 = 0.f;
#pragma unroll
    for (int i = 0; i < 8; i++) { sum += rs[i]; sum2 += rs2[i]; }
    m = sum * (1.0f / 256.0f);
    float var = sum2 * (1.0f / 256.0f) - m * m;
    inv = rsqrtf(var + 1e-5f);
    __syncthreads();
}

__device__ __forceinline__ uint32_t f2tf(float f) {
    uint32_t u;
    asm("cvt.rna.tf32.f32 %0, %1;" : "=r"(u) : "f"(f));
    return u;
}

__device__ __forceinline__ void mma_tf32(float* c, const uint32_t* a, const uint32_t* b) {
    asm volatile("mma.sync.aligned.m16n8k8.row.col.f32.tf32.tf32.f32 "
        "{%0,%1,%2,%3}, {%4,%5,%6,%7}, {%8,%9}, {%0,%1,%2,%3};"
        : "+f"(c[0]), "+f"(c[1]), "+f"(c[2]), "+f"(c[3])
        : "r"(a[0]), "r"(a[1]), "r"(a[2]), "r"(a[3]), "r"(b[0]), "r"(b[1]));
}

// ---------------- 1) LN over inputs ----------------
__global__ void __launch_bounds__(256) ln_input_kernel(const float* __restrict__ x,
                                                       const float* __restrict__ g,
                                                       const float* __restrict__ b) {
    __shared__ float rs[8], rs2[8];
    int row = blockIdx.x;
    int t   = threadIdx.x;
    float v = x[(size_t)row * DD + t];
    float m, inv;
    block_stats(v, rs, rs2, t, m, inv);
    g_x[(size_t)row * DD + t] = (v - m) * inv * g[t] + b[t];
}

// ---------------- 2) TF32 GEMM: {g_k,g_v}[M,256] = g_x @ {Wk,Wv} + bias ----------------
// BM=128, BN=128, BK=32, 256 threads, mma.m16n8k8.tf32
__global__ void __launch_bounds__(256) gemm_tf32_kernel(const float* __restrict__ Wk,
                                                        const float* __restrict__ bk,
                                                        const float* __restrict__ Wv,
                                                        const float* __restrict__ bv) {
    __shared__ uint32_t As[32][136];   // [k][m], pad 8 for conflict-free frag loads
    __shared__ uint32_t Bs[32][136];   // [k][n]

    int t = threadIdx.x;
    int mat = blockIdx.x >> 1;
    const float* W    = mat ? Wv : Wk;
    const float* bias = mat ? bv : bk;
    float* C          = mat ? g_v : g_k;
    int nbase = (blockIdx.x & 1) * 128;
    size_t mbase = (size_t)blockIdx.y * 128;

    int wid = t >> 5, lane = t & 31;
    int wm = (wid >> 1) * 32;
    int wn = (wid & 1) * 64;
    int qrow = lane >> 2;
    int qk   = lane & 3;

    float c[2][8][4];
#pragma unroll
    for (int mt = 0; mt < 2; mt++)
#pragma unroll
        for (int nt = 0; nt < 8; nt++)
#pragma unroll
            for (int i = 0; i < 4; i++) c[mt][nt][i] = 0.f;

    int am  = t >> 1;
    int akc = (t & 1) * 16;
    const float* ap = g_x + (mbase + am) * 256 + akc;
    int bkr = t >> 3;
    int bn0 = (t & 7) * 16;
    const float* wp = W + (size_t)bkr * 256 + nbase + bn0;

    for (int k0 = 0; k0 < 256; k0 += 32) {
        __syncthreads();
#pragma unroll
        for (int j = 0; j < 4; j++) {
            float4 va = *(const float4*)(ap + k0 + j * 4);
            As[akc + j*4 + 0][am] = f2tf(va.x);
            As[akc + j*4 + 1][am] = f2tf(va.y);
            As[akc + j*4 + 2][am] = f2tf(va.z);
            As[akc + j*4 + 3][am] = f2tf(va.w);
            float4 vb = *(const float4*)(wp + (size_t)k0 * 256 + j * 4);
            Bs[bkr][bn0 + j*4 + 0] = f2tf(vb.x);
            Bs[bkr][bn0 + j*4 + 1] = f2tf(vb.y);
            Bs[bkr][bn0 + j*4 + 2] = f2tf(vb.z);
            Bs[bkr][bn0 + j*4 + 3] = f2tf(vb.w);
        }
        __syncthreads();

#pragma unroll
        for (int ks = 0; ks < 4; ks++) {
            int kb = ks * 8;
            uint32_t a[2][4], b[8][2];
#pragma unroll
            for (int mt = 0; mt < 2; mt++) {
                int m = wm + mt * 16 + qrow;
                a[mt][0] = As[kb + qk][m];
                a[mt][1] = As[kb + qk][m + 8];
                a[mt][2] = As[kb + qk + 4][m];
                a[mt][3] = As[kb + qk + 4][m + 8];
            }
#pragma unroll
            for (int nt = 0; nt < 8; nt++) {
                int n = wn + nt * 8 + qrow;
                b[nt][0] = Bs[kb + qk][n];
                b[nt][1] = Bs[kb + qk + 4][n];
            }
#pragma unroll
            for (int mt = 0; mt < 2; mt++)
#pragma unroll
                for (int nt = 0; nt < 8; nt++)
                    mma_tf32(c[mt][nt], a[mt], b[nt]);
        }
    }

#pragma unroll
    for (int mt = 0; mt < 2; mt++) {
        int r0 = wm + mt * 16 + qrow;
#pragma unroll
        for (int nt = 0; nt < 8; nt++) {
            int col = nbase + wn + nt * 8 + 2 * qk;
            float b0v = bias[col], b1v = bias[col + 1];
            size_t base0 = (mbase + r0) * 256 + col;
            size_t base1 = (mbase + r0 + 8) * 256 + col;
            *(float2*)(C + base0) = make_float2(c[mt][nt][0] + b0v, c[mt][nt][1] + b1v);
            *(float2*)(C + base1) = make_float2(c[mt][nt][2] + b0v, c[mt][nt][3] + b1v);
        }
    }
}

// ---------------- 3) init kernels ----------------
__global__ void sem_init_kernel(const float* __restrict__ mu) {
    int r = blockIdx.x;
    int i = r & 7;
    g_sem_slots[(size_t)r * DD + threadIdx.x] = mu[i * DD + threadIdx.x];
}

__global__ void inst_init_kernel(const float* __restrict__ mu,
                                 const float* __restrict__ sigma,
                                 const float* __restrict__ noise) {
    size_t idx = (size_t)blockIdx.x * 256 + threadIdx.x;
    int d = idx & 255;
    int s = (idx >> 10) & 7;
    g_inst_slots[idx] = mu[s * DD + d] + expf(sigma[s * DD + d]) * noise[idx];
}

// ---------------- 4) q projection (+ zero acc/rowsum for next phase) ----------------
__device__ __forceinline__ void slot_q_impl(const float* __restrict__ slots,
                                            float* __restrict__ q,
                                            const float* __restrict__ lng,
                                            const float* __restrict__ lnb,
                                            const float* __restrict__ Wq,
                                            const float* __restrict__ bq) {
    __shared__ float sln[4][DD];
    __shared__ float rs[8], rs2[8];
    int t  = threadIdx.x;
    int r0 = blockIdx.x * 4;
    float gg = lng[t], bb = lnb[t];

#pragma unroll
    for (int r = 0; r < 4; r++) {
        float v = slots[(size_t)(r0 + r) * DD + t];
        float m, inv;
        block_stats(v, rs, rs2, t, m, inv);
        sln[r][t] = (v - m) * inv * gg + bb;
    }
    __syncthreads();

    float a0 = 0.f, a1 = 0.f, a2 = 0.f, a3 = 0.f;
#pragma unroll 4
    for (int d = 0; d < DD; d++) {
        float wv = Wq[d * DD + t];
        a0 += sln[0][d] * wv;
        a1 += sln[1][d] * wv;
        a2 += sln[2][d] * wv;
        a3 += sln[3][d] * wv;
    }
    float qb = bq[t];
    q[(size_t)(r0 + 0) * DD + t] = a0 + qb;
    q[(size_t)(r0 + 1) * DD + t] = a1 + qb;
    q[(size_t)(r0 + 2) * DD + t] = a2 + qb;
    q[(size_t)(r0 + 3) * DD + t] = a3 + qb;
}

__global__ void __launch_bounds__(256) sem_q_kernel(const float* lng, const float* lnb,
                                                    const float* Wq, const float* bq) {
    int gidx = blockIdx.x * 256 + threadIdx.x;   // 32 blocks -> 8192 threads
#pragma unroll
    for (int i = 0; i < 4; i++) g_sem_acc[gidx + i * 8192] = 0.f;
    if (gidx < BB * NSL) g_sem_rowsum[gidx] = 0.f;
    slot_q_impl(g_sem_slots, g_sem_q, lng, lnb, Wq, bq);
}
__global__ void __launch_bounds__(256) inst_q_kernel(const float* lng, const float* lnb,
                                                     const float* Wq, const float* bq) {
    int gidx = blockIdx.x * 256 + threadIdx.x;   // 128 blocks -> 32768 threads
#pragma unroll
    for (int i = 0; i < 4; i++) g_inst_acc[gidx + i * 32768] = 0.f;
    if (gidx < BB * NSL * NPI) g_inst_rowsum[gidx] = 0.f;
    slot_q_impl(g_inst_slots, g_inst_q, lng, lnb, Wq, bq);
}

// ---------------- 5) fused sem: dots + softmax(slots) + eps + rowsum + update ----------------
__global__ void __launch_bounds__(256) sem_fused_kernel(int write_dots) {
    int b  = blockIdx.y;
    int n0 = blockIdx.x * 256;
    int t  = threadIdx.x;
    int n  = n0 + t;

    __shared__ float qs[NSL][256];   // q tiles, reused as attn tile
    for (int idx = t; idx < NSL * DD; idx += 256)
        qs[idx >> 8][idx & 255] = g_sem_q[(size_t)b * NSL * DD + idx];
    __syncthreads();

    float acc[NSL];
#pragma unroll
    for (int i = 0; i < NSL; i++) acc[i] = 0.f;

    const float* kp = g_k + ((size_t)b * NN + n) * DD;
#pragma unroll 1
    for (int d0 = 0; d0 < DD; d0 += 16) {
        float4 k0 = *(const float4*)(kp + d0);
        float4 k1 = *(const float4*)(kp + d0 + 4);
        float4 k2 = *(const float4*)(kp + d0 + 8);
        float4 k3 = *(const float4*)(kp + d0 + 12);
#pragma unroll
        for (int i = 0; i < NSL; i++) {
            float4 q0 = *(const float4*)&qs[i][d0];
            float4 q1 = *(const float4*)&qs[i][d0 + 4];
            float4 q2 = *(const float4*)&qs[i][d0 + 8];
            float4 q3 = *(const float4*)&qs[i][d0 + 12];
            acc[i] += k0.x * q0.x + k0.y * q0.y + k0.z * q0.z + k0.w * q0.w
                    + k1.x * q1.x + k1.y * q1.y + k1.z * q1.z + k1.w * q1.w
                    + k2.x * q2.x + k2.y * q2.y + k2.z * q2.z + k2.w * q2.w
                    + k3.x * q3.x + k3.y * q3.y + k3.z * q3.z + k3.w * q3.w;
        }
    }

    float dv[NSL], e[NSL];
    float mx = -1e30f;
#pragma unroll
    for (int i = 0; i < NSL; i++) { dv[i] = acc[i] * SCALE_F; mx = fmaxf(mx, dv[i]); }
    float ssum = 0.f;
#pragma unroll
    for (int i = 0; i < NSL; i++) { e[i] = expf(dv[i] - mx); ssum += e[i]; }
    float inv = 1.0f / ssum;

    size_t base = (size_t)b * NSL * NN + n;
    int l = t & 31;
    float at[NSL];
#pragma unroll
    for (int i = 0; i < NSL; i++) {
        at[i] = e[i] * inv + EPS_F;
        if (write_dots) g_sem_dots[base + (size_t)i * NN] = dv[i];
        float sv = warp_sum(at[i]);
        if (l == 0) atomicAdd(&g_sem_rowsum[b * NSL + i], sv);
    }

    __syncthreads();   // all q reads done
#pragma unroll
    for (int i = 0; i < NSL; i++) qs[i][t] = at[i];
    __syncthreads();

    // update: acc2[i] = sum_n attn[i,n] * v[n, d=t]
    float acc2[NSL];
#pragma unroll
    for (int i = 0; i < NSL; i++) acc2[i] = 0.f;
    const float* vp = g_v + ((size_t)b * NN + n0) * DD + t;
#pragma unroll 1
    for (int nn = 0; nn < 256; nn += 4) {
        float v0 = vp[(size_t)(nn + 0) * DD];
        float v1 = vp[(size_t)(nn + 1) * DD];
        float v2 = vp[(size_t)(nn + 2) * DD];
        float v3 = vp[(size_t)(nn + 3) * DD];
#pragma unroll
        for (int i = 0; i < NSL; i++) {
            float4 a4 = *(const float4*)&qs[i][nn];
            acc2[i] += v0 * a4.x + v1 * a4.y + v2 * a4.z + v3 * a4.w;
        }
    }
#pragma unroll
    for (int i = 0; i < NSL; i++)
        atomicAdd(&g_sem_acc[(size_t)(b * NSL + i) * DD + t], acc2[i]);
}

// ---------------- 6) slots = s1 + MLP(LN(s1)), s1 = slots + acc/rowsum ----------------
__device__ __forceinline__ void slot_mlp_impl(float* __restrict__ slots,
                                              const float* __restrict__ acc,
                                              const float* __restrict__ rowsum,
                                              const float* __restrict__ lng,
                                              const float* __restrict__ lnb,
                                              const float* __restrict__ W1,
                                              const float* __restrict__ b1,
                                              const float* __restrict__ W2,
                                              const float* __restrict__ b2) {
    __shared__ float s1[4][DD];
    __shared__ float sln[4][DD];
    __shared__ float hs[4][HH];
    __shared__ float rs[8], rs2[8];
    int t  = threadIdx.x;
    int r0 = blockIdx.x * 4;
    float gg = lng[t], bb = lnb[t];

#pragma unroll
    for (int r = 0; r < 4; r++) {
        int row = r0 + r;
        float v = slots[(size_t)row * DD + t] + acc[(size_t)row * DD + t] / rowsum[row];
        s1[r][t] = v;
        float m, inv;
        block_stats(v, rs, rs2, t, m, inv);
        sln[r][t] = (v - m) * inv * gg + bb;
    }
    __syncthreads();

    float h0 = 0.f, h1 = 0.f, h2 = 0.f, h3 = 0.f;
#pragma unroll 4
    for (int d = 0; d < DD; d++) {
        float wv = W1[d * HH + t];
        h0 += sln[0][d] * wv;
        h1 += sln[1][d] * wv;
        h2 += sln[2][d] * wv;
        h3 += sln[3][d] * wv;
    }
    float b1v = b1[t];
    hs[0][t] = fmaxf(h0 + b1v, 0.f);
    hs[1][t] = fmaxf(h1 + b1v, 0.f);
    hs[2][t] = fmaxf(h2 + b1v, 0.f);
    hs[3][t] = fmaxf(h3 + b1v, 0.f);
    __syncthreads();

    float o0 = 0.f, o1 = 0.f, o2 = 0.f, o3 = 0.f;
#pragma unroll 4
    for (int j = 0; j < HH; j++) {
        float wv = W2[j * DD + t];
        o0 += hs[0][j] * wv;
        o1 += hs[1][j] * wv;
        o2 += hs[2][j] * wv;
        o3 += hs[3][j] * wv;
    }
    float b2v = b2[t];
    slots[(size_t)(r0 + 0) * DD + t] = s1[0][t] + o0 + b2v;
    slots[(size_t)(r0 + 1) * DD + t] = s1[1][t] + o1 + b2v;
    slots[(size_t)(r0 + 2) * DD + t] = s1[2][t] + o2 + b2v;
    slots[(size_t)(r0 + 3) * DD + t] = s1[3][t] + o3 + b2v;
}

__global__ void __launch_bounds__(256) sem_mlp_kernel(const float* lng, const float* lnb,
                                                      const float* W1, const float* b1,
                                                      const float* W2, const float* b2) {
    slot_mlp_impl(g_sem_slots, g_sem_acc, g_sem_rowsum, lng, lnb, W1, b1, W2, b2);
}
__global__ void __launch_bounds__(256) inst_mlp_kernel(const float* lng, const float* lnb,
                                                       const float* W1, const float* b1,
                                                       const float* W2, const float* b2) {
    slot_mlp_impl(g_inst_slots, g_inst_acc, g_inst_rowsum, lng, lnb, W1, b1, W2, b2);
}

// ---------------- 7) fused inst: dots + softmax(NP)*sem_w + rowsum + update ----------------
__global__ void __launch_bounds__(256) inst_fused_kernel(int write_dots) {
    int b  = blockIdx.y;
    int n0 = blockIdx.x * 256;
    int t  = threadIdx.x;
    int n  = n0 + t;

    __shared__ float qs[NSL * NPI][256];   // 32 KB, reused as attn tile
    for (int idx = t; idx < 32 * DD; idx += 256)
        qs[idx >> 8][idx & 255] = g_inst_q[(size_t)b * 32 * DD + idx];
    __syncthreads();

    float acc[32];
#pragma unroll
    for (int i = 0; i < 32; i++) acc[i] = 0.f;

    const float* kp = g_k + ((size_t)b * NN + n) * DD;
#pragma unroll 1
    for (int d0 = 0; d0 < DD; d0 += 16) {
        float4 k0 = *(const float4*)(kp + d0);
        float4 k1 = *(const float4*)(kp + d0 + 4);
        float4 k2 = *(const float4*)(kp + d0 + 8);
        float4 k3 = *(const float4*)(kp + d0 + 12);
#pragma unroll
        for (int i = 0; i < 32; i++) {
            float4 q0 = *(const float4*)&qs[i][d0];
            float4 q1 = *(const float4*)&qs[i][d0 + 4];
            float4 q2 = *(const float4*)&qs[i][d0 + 8];
            float4 q3 = *(const float4*)&qs[i][d0 + 12];
            acc[i] += k0.x * q0.x + k0.y * q0.y + k0.z * q0.z + k0.w * q0.w
                    + k1.x * q1.x + k1.y * q1.y + k1.z * q1.z + k1.w * q1.w
                    + k2.x * q2.x + k2.y * q2.y + k2.z * q2.z + k2.w * q2.w
                    + k3.x * q3.x + k3.y * q3.y + k3.z * q3.z + k3.w * q3.w;
        }
    }

    // sem_w on the fly: softmax over slots of final sem dots
    float wv[NSL];
    {
        size_t sbase = (size_t)b * NSL * NN + n;
        float sdv[NSL];
        float smx = -1e30f;
#pragma unroll
        for (int i = 0; i < NSL; i++) { sdv[i] = g_sem_dots[sbase + (size_t)i * NN]; smx = fmaxf(smx, sdv[i]); }
        float ss = 0.f;
#pragma unroll
        for (int i = 0; i < NSL; i++) { sdv[i] = expf(sdv[i] - smx); ss += sdv[i]; }
        float sinv = 1.0f / ss;
#pragma unroll
        for (int i = 0; i < NSL; i++) wv[i] = sdv[i] * sinv;
    }

    size_t dbase = (size_t)b * 32 * NN + n;
    int l = t & 31;
    float at[32];
#pragma unroll
    for (int s = 0; s < 8; s++) {
        float dv[NPI], e[NPI];
        float mx = -1e30f;
#pragma unroll
        for (int p = 0; p < NPI; p++) { dv[p] = acc[s * 4 + p] * SCALE_F; mx = fmaxf(mx, dv[p]); }
        float ssum = 0.f;
#pragma unroll
        for (int p = 0; p < NPI; p++) { e[p] = expf(dv[p] - mx); ssum += e[p]; }
        float invs = 1.0f / ssum;
#pragma unroll
        for (int p = 0; p < NPI; p++) {
            int sp = s * 4 + p;
            at[sp] = (e[p] * invs + EPS_F) * wv[s];
            if (write_dots) g_inst_dots[dbase + (size_t)sp * NN] = dv[p];
            float sv = warp_sum(at[sp]);
            if (l == 0) atomicAdd(&g_inst_rowsum[b * 32 + sp], sv);
        }
    }

    __syncthreads();   // all q reads done
#pragma unroll
    for (int i = 0; i < 32; i++) qs[i][t] = at[i];
    __syncthreads();

    float acc2[32];
#pragma unroll
    for (int i = 0; i < 32; i++) acc2[i] = 0.f;
    const float* vp = g_v + ((size_t)b * NN + n0) * DD + t;
#pragma unroll 1
    for (int nn = 0; nn < 256; nn += 4) {
        float v0 = vp[(size_t)(nn + 0) * DD];
        float v1 = vp[(size_t)(nn + 1) * DD];
        float v2 = vp[(size_t)(nn + 2) * DD];
        float v3 = vp[(size_t)(nn + 3) * DD];
#pragma unroll
        for (int i = 0; i < 32; i++) {
            float4 a4 = *(const float4*)&qs[i][nn];
            acc2[i] += v0 * a4.x + v1 * a4.y + v2 * a4.z + v3 * a4.w;
        }
    }
#pragma unroll
    for (int i = 0; i < 32; i++)
        atomicAdd(&g_inst_acc[(size_t)(b * 32 + i) * DD + t], acc2[i]);
}

// ---------------- 8) assemble output ----------------
__global__ void __launch_bounds__(256) write_out_kernel(float* __restrict__ out) {
    size_t idx = (size_t)blockIdx.x * 256 + threadIdx.x;
    const size_t A1 = 32768;
    const size_t A2 = 557056;
    const size_t A3 = 688128;
    const size_t A4 = 2785280;
    if (idx >= A4) return;
    float v;
    if (idx < A1)      v = g_sem_slots[idx];
    else if (idx < A2) v = g_sem_dots[idx - A1];
    else if (idx < A3) v = g_inst_slots[idx - A2];
    else               v = g_inst_dots[idx - A3];
    out[idx] = v;
}

// ---------------- launch ----------------
extern "C" void kernel_launch(void* const* d_in, const int* in_sizes, int n_in,
                              void* d_out, int out_size) {
    (void)in_sizes; (void)n_in; (void)out_size;
    const float* inputs      = (const float*)d_in[0];
    const float* noise       = (const float*)d_in[3];
    const float* ln_in_g     = (const float*)d_in[4];
    const float* ln_in_b     = (const float*)d_in[5];
    const float* ln_s_g      = (const float*)d_in[6];
    const float* ln_s_b      = (const float*)d_in[7];
    const float* ln_ff_g     = (const float*)d_in[8];
    const float* ln_ff_b     = (const float*)d_in[9];
    const float* slots_mu    = (const float*)d_in[10];
    const float* slots_sigma = (const float*)d_in[11];
    const float* Wq          = (const float*)d_in[12];
    const float* bq          = (const float*)d_in[13];
    const float* Wk          = (const float*)d_in[14];
    const float* bk          = (const float*)d_in[15];
    const float* Wv          = (const float*)d_in[16];
    const float* bv          = (const float*)d_in[17];
    const float* W1          = (const float*)d_in[18];
    const float* b1          = (const float*)d_in[19];
    const float* W2          = (const float*)d_in[20];
    const float* b2          = (const float*)d_in[21];
    float* out = (float*)d_out;

    ln_input_kernel<<<BB * NN, 256>>>(inputs, ln_in_g, ln_in_b);

    dim3 gemm_grid(4, 512);
    gemm_tf32_kernel<<<gemm_grid, 256>>>(Wk, bk, Wv, bv);

    sem_init_kernel<<<BB * NSL, 256>>>(slots_mu);

    dim3 bn_grid(16, 16);
    for (int it = 0; it < 3; it++) {
        sem_q_kernel<<<BB * NSL / 4, 256>>>(ln_s_g, ln_s_b, Wq, bq);
        sem_fused_kernel<<<bn_grid, 256>>>(it == 2 ? 1 : 0);
        sem_mlp_kernel<<<BB * NSL / 4, 256>>>(ln_ff_g, ln_ff_b, W1, b1, W2, b2);
    }

    inst_init_kernel<<<BB * NSL * NPI, 256>>>(slots_mu, slots_sigma, noise);

    for (int it = 0; it < 3; it++) {
        inst_q_kernel<<<BB * NSL * NPI / 4, 256>>>(ln_s_g, ln_s_b, Wq, bq);
        inst_fused_kernel<<<bn_grid, 256>>>(it == 2 ? 1 : 0);
        inst_mlp_kernel<<<BB * NSL * NPI / 4, 256>>>(ln_ff_g, ln_ff_b, W1, b1, W2, b2);
    }

    write_out_kernel<<<10880, 256>>>(out);
}

// round 3
// speedup vs baseline: 1.3986x; 1.1362x over previous
#include <cuda_runtime.h>
#include <math.h>
#include <stdint.h>

#define BB   16
#define NN   4096
#define DD   256
#define NSL  8
#define NPI  4
#define HH   256
#define SCALE_F 0.0625f
#define EPS_F   1e-8f

#define KT_PITCH 36   // 32 floats + 4 pad; 144B rows keep 16B alignment

// ---------------- scratch ----------------
__device__ float g_x[BB*NN*DD];
__device__ float g_k[BB*NN*DD];
__device__ float g_v[BB*NN*DD];

__device__ float g_sem_slots[BB*NSL*DD];
__device__ float g_sem_q[BB*NSL*DD];
__device__ float g_sem_dots[BB*NSL*NN];
__device__ float g_sem_rowsum[BB*NSL];
__device__ float g_sem_acc[BB*NSL*DD];

__device__ float g_inst_slots[BB*NSL*NPI*DD];
__device__ float g_inst_q[BB*NSL*NPI*DD];
__device__ float g_inst_dots[BB*NSL*NPI*NN];
__device__ float g_inst_rowsum[BB*NSL*NPI];
__device__ float g_inst_acc[BB*NSL*NPI*DD];

// ---------------- helpers ----------------
__device__ __forceinline__ float warp_sum(float v) {
#pragma unroll
    for (int o = 16; o; o >>= 1) v += __shfl_xor_sync(0xffffffffu, v, o);
    return v;
}

__device__ __forceinline__ void block_stats(float v, float* rs, float* rs2, int t,
                                            float& m, float& inv) {
    float s  = warp_sum(v);
    float s2 = warp_sum(v * v);
    if ((t & 31) == 0) { rs[t >> 5] = s; rs2[t >> 5] = s2; }
    __syncthreads();
    float sum = 0.f, sum2 = 0.f;
#pragma unroll
    for (int i = 0; i < 8; i++) { sum += rs[i]; sum2 += rs2[i]; }
    m = sum * (1.0f / 256.0f);
    float var = sum2 * (1.0f / 256.0f) - m * m;
    inv = rsqrtf(var + 1e-5f);
    __syncthreads();
}

__device__ __forceinline__ uint32_t f2tf(float f) {
    uint32_t u;
    asm("cvt.rna.tf32.f32 %0, %1;" : "=r"(u) : "f"(f));
    return u;
}

__device__ __forceinline__ void mma_tf32(float* c, const uint32_t* a, const uint32_t* b) {
    asm volatile("mma.sync.aligned.m16n8k8.row.col.f32.tf32.tf32.f32 "
        "{%0,%1,%2,%3}, {%4,%5,%6,%7}, {%8,%9}, {%0,%1,%2,%3};"
        : "+f"(c[0]), "+f"(c[1]), "+f"(c[2]), "+f"(c[3])
        : "r"(a[0]), "r"(a[1]), "r"(a[2]), "r"(a[3]), "r"(b[0]), "r"(b[1]));
}

// ---------------- 1) LN over inputs ----------------
__global__ void __launch_bounds__(256) ln_input_kernel(const float* __restrict__ x,
                                                       const float* __restrict__ g,
                                                       const float* __restrict__ b) {
    __shared__ float rs[8], rs2[8];
    int row = blockIdx.x;
    int t   = threadIdx.x;
    float v = x[(size_t)row * DD + t];
    float m, inv;
    block_stats(v, rs, rs2, t, m, inv);
    g_x[(size_t)row * DD + t] = (v - m) * inv * g[t] + b[t];
}

// ---------------- 2) TF32 GEMM: {g_k,g_v}[M,256] = g_x @ {Wk,Wv} + bias ----------------
__global__ void __launch_bounds__(256) gemm_tf32_kernel(const float* __restrict__ Wk,
                                                        const float* __restrict__ bk,
                                                        const float* __restrict__ Wv,
                                                        const float* __restrict__ bv) {
    __shared__ uint32_t As[32][136];
    __shared__ uint32_t Bs[32][136];

    int t = threadIdx.x;
    int mat = blockIdx.x >> 1;
    const float* W    = mat ? Wv : Wk;
    const float* bias = mat ? bv : bk;
    float* C          = mat ? g_v : g_k;
    int nbase = (blockIdx.x & 1) * 128;
    size_t mbase = (size_t)blockIdx.y * 128;

    int wid = t >> 5, lane = t & 31;
    int wm = (wid >> 1) * 32;
    int wn = (wid & 1) * 64;
    int qrow = lane >> 2;
    int qk   = lane & 3;

    float c[2][8][4];
#pragma unroll
    for (int mt = 0; mt < 2; mt++)
#pragma unroll
        for (int nt = 0; nt < 8; nt++)
#pragma unroll
            for (int i = 0; i < 4; i++) c[mt][nt][i] = 0.f;

    int am  = t >> 1;
    int akc = (t & 1) * 16;
    const float* ap = g_x + (mbase + am) * 256 + akc;
    int bkr = t >> 3;
    int bn0 = (t & 7) * 16;
    const float* wp = W + (size_t)bkr * 256 + nbase + bn0;

    for (int k0 = 0; k0 < 256; k0 += 32) {
        __syncthreads();
#pragma unroll
        for (int j = 0; j < 4; j++) {
            float4 va = *(const float4*)(ap + k0 + j * 4);
            As[akc + j*4 + 0][am] = f2tf(va.x);
            As[akc + j*4 + 1][am] = f2tf(va.y);
            As[akc + j*4 + 2][am] = f2tf(va.z);
            As[akc + j*4 + 3][am] = f2tf(va.w);
            float4 vb = *(const float4*)(wp + (size_t)k0 * 256 + j * 4);
            Bs[bkr][bn0 + j*4 + 0] = f2tf(vb.x);
            Bs[bkr][bn0 + j*4 + 1] = f2tf(vb.y);
            Bs[bkr][bn0 + j*4 + 2] = f2tf(vb.z);
            Bs[bkr][bn0 + j*4 + 3] = f2tf(vb.w);
        }
        __syncthreads();

#pragma unroll
        for (int ks = 0; ks < 4; ks++) {
            int kb = ks * 8;
            uint32_t a[2][4], b[8][2];
#pragma unroll
            for (int mt = 0; mt < 2; mt++) {
                int m = wm + mt * 16 + qrow;
                a[mt][0] = As[kb + qk][m];
                a[mt][1] = As[kb + qk][m + 8];
                a[mt][2] = As[kb + qk + 4][m];
                a[mt][3] = As[kb + qk + 4][m + 8];
            }
#pragma unroll
            for (int nt = 0; nt < 8; nt++) {
                int n = wn + nt * 8 + qrow;
                b[nt][0] = Bs[kb + qk][n];
                b[nt][1] = Bs[kb + qk + 4][n];
            }
#pragma unroll
            for (int mt = 0; mt < 2; mt++)
#pragma unroll
                for (int nt = 0; nt < 8; nt++)
                    mma_tf32(c[mt][nt], a[mt], b[nt]);
        }
    }

#pragma unroll
    for (int mt = 0; mt < 2; mt++) {
        int r0 = wm + mt * 16 + qrow;
#pragma unroll
        for (int nt = 0; nt < 8; nt++) {
            int col = nbase + wn + nt * 8 + 2 * qk;
            float b0v = bias[col], b1v = bias[col + 1];
            size_t base0 = (mbase + r0) * 256 + col;
            size_t base1 = (mbase + r0 + 8) * 256 + col;
            *(float2*)(C + base0) = make_float2(c[mt][nt][0] + b0v, c[mt][nt][1] + b1v);
            *(float2*)(C + base1) = make_float2(c[mt][nt][2] + b0v, c[mt][nt][3] + b1v);
        }
    }
}

// ---------------- 3) init kernels ----------------
__global__ void sem_init_kernel(const float* __restrict__ mu) {
    int r = blockIdx.x;
    int i = r & 7;
    g_sem_slots[(size_t)r * DD + threadIdx.x] = mu[i * DD + threadIdx.x];
}

__global__ void inst_init_kernel(const float* __restrict__ mu,
                                 const float* __restrict__ sigma,
                                 const float* __restrict__ noise) {
    size_t idx = (size_t)blockIdx.x * 256 + threadIdx.x;
    int d = idx & 255;
    int s = (idx >> 10) & 7;
    g_inst_slots[idx] = mu[s * DD + d] + expf(sigma[s * DD + d]) * noise[idx];
}

// ---------------- 4) q projection (+ zero acc/rowsum) ----------------
__device__ __forceinline__ void slot_q_impl(const float* __restrict__ slots,
                                            float* __restrict__ q,
                                            const float* __restrict__ lng,
                                            const float* __restrict__ lnb,
                                            const float* __restrict__ Wq,
                                            const float* __restrict__ bq) {
    __shared__ float sln[4][DD];
    __shared__ float rs[8], rs2[8];
    int t  = threadIdx.x;
    int r0 = blockIdx.x * 4;
    float gg = lng[t], bb = lnb[t];

#pragma unroll
    for (int r = 0; r < 4; r++) {
        float v = slots[(size_t)(r0 + r) * DD + t];
        float m, inv;
        block_stats(v, rs, rs2, t, m, inv);
        sln[r][t] = (v - m) * inv * gg + bb;
    }
    __syncthreads();

    float a0 = 0.f, a1 = 0.f, a2 = 0.f, a3 = 0.f;
#pragma unroll 1
    for (int d0 = 0; d0 < DD; d0 += 16) {
        float w[16];
#pragma unroll
        for (int j = 0; j < 16; j++) w[j] = Wq[(d0 + j) * DD + t];
#pragma unroll
        for (int j = 0; j < 16; j++) {
            a0 += sln[0][d0 + j] * w[j];
            a1 += sln[1][d0 + j] * w[j];
            a2 += sln[2][d0 + j] * w[j];
            a3 += sln[3][d0 + j] * w[j];
        }
    }
    float qb = bq[t];
    q[(size_t)(r0 + 0) * DD + t] = a0 + qb;
    q[(size_t)(r0 + 1) * DD + t] = a1 + qb;
    q[(size_t)(r0 + 2) * DD + t] = a2 + qb;
    q[(size_t)(r0 + 3) * DD + t] = a3 + qb;
}

__global__ void __launch_bounds__(256) sem_q_kernel(const float* lng, const float* lnb,
                                                    const float* Wq, const float* bq) {
    int gidx = blockIdx.x * 256 + threadIdx.x;
#pragma unroll
    for (int i = 0; i < 4; i++) g_sem_acc[gidx + i * 8192] = 0.f;
    if (gidx < BB * NSL) g_sem_rowsum[gidx] = 0.f;
    slot_q_impl(g_sem_slots, g_sem_q, lng, lnb, Wq, bq);
}
__global__ void __launch_bounds__(256) inst_q_kernel(const float* lng, const float* lnb,
                                                     const float* Wq, const float* bq) {
    int gidx = blockIdx.x * 256 + threadIdx.x;
#pragma unroll
    for (int i = 0; i < 4; i++) g_inst_acc[gidx + i * 32768] = 0.f;
    if (gidx < BB * NSL * NPI) g_inst_rowsum[gidx] = 0.f;
    slot_q_impl(g_inst_slots, g_inst_q, lng, lnb, Wq, bq);
}

// ---------------- shared: k-tile staged dots accumulation ----------------
// qs: [NR][256] q vectors; kt: [256][KT_PITCH] staging. acc[i] += k[n=t] . q[i]
template<int NR>
__device__ __forceinline__ void dots_accum(const float* __restrict__ kbase,
                                           const float* __restrict__ qs,
                                           float* __restrict__ kt,
                                           float* acc, int t) {
#pragma unroll 1
    for (int dt = 0; dt < DD; dt += 32) {
        __syncthreads();
#pragma unroll
        for (int j = 0; j < 8; j++) {
            int idx = t + j * 256;           // 0..2047
            int row = idx >> 3;
            int c   = (idx & 7) * 4;
            float4 kv = *(const float4*)(kbase + (size_t)row * DD + dt + c);
            *(float4*)&kt[row * KT_PITCH + c] = kv;
        }
        __syncthreads();
#pragma unroll
        for (int d0 = 0; d0 < 32; d0 += 4) {
            float4 kv = *(const float4*)&kt[t * KT_PITCH + d0];
#pragma unroll
            for (int i = 0; i < NR; i++) {
                float4 qv = *(const float4*)&qs[i * 256 + dt + d0];
                acc[i] += kv.x * qv.x + kv.y * qv.y + kv.z * qv.z + kv.w * qv.w;
            }
        }
    }
}

// ---------------- 5) fused sem: dots + softmax(slots) + rowsum + update ----------------
__global__ void __launch_bounds__(256) sem_fused_kernel(int write_dots) {
    extern __shared__ float smem[];
    float* qs = smem;                 // [NSL][256]
    float* kt = smem + NSL * 256;     // [256][KT_PITCH]

    int b  = blockIdx.y;
    int n0 = blockIdx.x * 256;
    int t  = threadIdx.x;
    int n  = n0 + t;

    for (int idx = t; idx < NSL * DD; idx += 256)
        qs[idx] = g_sem_q[(size_t)b * NSL * DD + idx];

    float acc[NSL];
#pragma unroll
    for (int i = 0; i < NSL; i++) acc[i] = 0.f;

    dots_accum<NSL>(g_k + ((size_t)b * NN + n0) * DD, qs, kt, acc, t);

    float dv[NSL], e[NSL];
    float mx = -1e30f;
#pragma unroll
    for (int i = 0; i < NSL; i++) { dv[i] = acc[i] * SCALE_F; mx = fmaxf(mx, dv[i]); }
    float ssum = 0.f;
#pragma unroll
    for (int i = 0; i < NSL; i++) { e[i] = expf(dv[i] - mx); ssum += e[i]; }
    float inv = 1.0f / ssum;

    size_t base = (size_t)b * NSL * NN + n;
    int l = t & 31;
    float at[NSL];
#pragma unroll
    for (int i = 0; i < NSL; i++) {
        at[i] = e[i] * inv + EPS_F;
        if (write_dots) g_sem_dots[base + (size_t)i * NN] = dv[i];
        float sv = warp_sum(at[i]);
        if (l == 0) atomicAdd(&g_sem_rowsum[b * NSL + i], sv);
    }

    __syncthreads();
#pragma unroll
    for (int i = 0; i < NSL; i++) qs[i * 256 + t] = at[i];
    __syncthreads();

    float acc2[NSL];
#pragma unroll
    for (int i = 0; i < NSL; i++) acc2[i] = 0.f;
    const float* vp = g_v + ((size_t)b * NN + n0) * DD + t;
#pragma unroll 1
    for (int nn = 0; nn < 256; nn += 4) {
        float v0 = vp[(size_t)(nn + 0) * DD];
        float v1 = vp[(size_t)(nn + 1) * DD];
        float v2 = vp[(size_t)(nn + 2) * DD];
        float v3 = vp[(size_t)(nn + 3) * DD];
#pragma unroll
        for (int i = 0; i < NSL; i++) {
            float4 a4 = *(const float4*)&qs[i * 256 + nn];
            acc2[i] += v0 * a4.x + v1 * a4.y + v2 * a4.z + v3 * a4.w;
        }
    }
#pragma unroll
    for (int i = 0; i < NSL; i++)
        atomicAdd(&g_sem_acc[(size_t)(b * NSL + i) * DD + t], acc2[i]);
}

// ---------------- 6) slot MLP ----------------
__device__ __forceinline__ void slot_mlp_impl(float* __restrict__ slots,
                                              const float* __restrict__ acc,
                                              const float* __restrict__ rowsum,
                                              const float* __restrict__ lng,
                                              const float* __restrict__ lnb,
                                              const float* __restrict__ W1,
                                              const float* __restrict__ b1,
                                              const float* __restrict__ W2,
                                              const float* __restrict__ b2) {
    __shared__ float s1[4][DD];
    __shared__ float sln[4][DD];
    __shared__ float hs[4][HH];
    __shared__ float rs[8], rs2[8];
    int t  = threadIdx.x;
    int r0 = blockIdx.x * 4;
    float gg = lng[t], bb = lnb[t];

#pragma unroll
    for (int r = 0; r < 4; r++) {
        int row = r0 + r;
        float v = slots[(size_t)row * DD + t] + acc[(size_t)row * DD + t] / rowsum[row];
        s1[r][t] = v;
        float m, inv;
        block_stats(v, rs, rs2, t, m, inv);
        sln[r][t] = (v - m) * inv * gg + bb;
    }
    __syncthreads();

    float h0 = 0.f, h1 = 0.f, h2 = 0.f, h3 = 0.f;
#pragma unroll 1
    for (int d0 = 0; d0 < DD; d0 += 16) {
        float w[16];
#pragma unroll
        for (int j = 0; j < 16; j++) w[j] = W1[(d0 + j) * HH + t];
#pragma unroll
        for (int j = 0; j < 16; j++) {
            h0 += sln[0][d0 + j] * w[j];
            h1 += sln[1][d0 + j] * w[j];
            h2 += sln[2][d0 + j] * w[j];
            h3 += sln[3][d0 + j] * w[j];
        }
    }
    float b1v = b1[t];
    hs[0][t] = fmaxf(h0 + b1v, 0.f);
    hs[1][t] = fmaxf(h1 + b1v, 0.f);
    hs[2][t] = fmaxf(h2 + b1v, 0.f);
    hs[3][t] = fmaxf(h3 + b1v, 0.f);
    __syncthreads();

    float o0 = 0.f, o1 = 0.f, o2 = 0.f, o3 = 0.f;
#pragma unroll 1
    for (int d0 = 0; d0 < HH; d0 += 16) {
        float w[16];
#pragma unroll
        for (int j = 0; j < 16; j++) w[j] = W2[(d0 + j) * DD + t];
#pragma unroll
        for (int j = 0; j < 16; j++) {
            o0 += hs[0][d0 + j] * w[j];
            o1 += hs[1][d0 + j] * w[j];
            o2 += hs[2][d0 + j] * w[j];
            o3 += hs[3][d0 + j] * w[j];
        }
    }
    float b2v = b2[t];
    slots[(size_t)(r0 + 0) * DD + t] = s1[0][t] + o0 + b2v;
    slots[(size_t)(r0 + 1) * DD + t] = s1[1][t] + o1 + b2v;
    slots[(size_t)(r0 + 2) * DD + t] = s1[2][t] + o2 + b2v;
    slots[(size_t)(r0 + 3) * DD + t] = s1[3][t] + o3 + b2v;
}

__global__ void __launch_bounds__(256) sem_mlp_kernel(const float* lng, const float* lnb,
                                                      const float* W1, const float* b1,
                                                      const float* W2, const float* b2) {
    slot_mlp_impl(g_sem_slots, g_sem_acc, g_sem_rowsum, lng, lnb, W1, b1, W2, b2);
}
__global__ void __launch_bounds__(256) inst_mlp_kernel(const float* lng, const float* lnb,
                                                       const float* W1, const float* b1,
                                                       const float* W2, const float* b2) {
    slot_mlp_impl(g_inst_slots, g_inst_acc, g_inst_rowsum, lng, lnb, W1, b1, W2, b2);
}

// ---------------- 7) fused inst: dots + softmax(NP)*sem_w + rowsum + update ----------------
__global__ void __launch_bounds__(256) inst_fused_kernel(int write_dots) {
    extern __shared__ float smem[];
    float* qs = smem;                 // [32][256]
    float* kt = smem + 32 * 256;      // [256][KT_PITCH]

    int b  = blockIdx.y;
    int n0 = blockIdx.x * 256;
    int t  = threadIdx.x;
    int n  = n0 + t;

    for (int idx = t; idx < 32 * DD; idx += 256)
        qs[idx] = g_inst_q[(size_t)b * 32 * DD + idx];

    float acc[32];
#pragma unroll
    for (int i = 0; i < 32; i++) acc[i] = 0.f;

    dots_accum<32>(g_k + ((size_t)b * NN + n0) * DD, qs, kt, acc, t);

    // sem_w on the fly
    float wv[NSL];
    {
        size_t sbase = (size_t)b * NSL * NN + n;
        float sdv[NSL];
        float smx = -1e30f;
#pragma unroll
        for (int i = 0; i < NSL; i++) { sdv[i] = g_sem_dots[sbase + (size_t)i * NN]; smx = fmaxf(smx, sdv[i]); }
        float ss = 0.f;
#pragma unroll
        for (int i = 0; i < NSL; i++) { sdv[i] = expf(sdv[i] - smx); ss += sdv[i]; }
        float sinv = 1.0f / ss;
#pragma unroll
        for (int i = 0; i < NSL; i++) wv[i] = sdv[i] * sinv;
    }

    size_t dbase = (size_t)b * 32 * NN + n;
    int l = t & 31;
    float at[32];
#pragma unroll
    for (int s = 0; s < 8; s++) {
        float dv[NPI], e[NPI];
        float mx = -1e30f;
#pragma unroll
        for (int p = 0; p < NPI; p++) { dv[p] = acc[s * 4 + p] * SCALE_F; mx = fmaxf(mx, dv[p]); }
        float ssum = 0.f;
#pragma unroll
        for (int p = 0; p < NPI; p++) { e[p] = expf(dv[p] - mx); ssum += e[p]; }
        float invs = 1.0f / ssum;
#pragma unroll
        for (int p = 0; p < NPI; p++) {
            int sp = s * 4 + p;
            at[sp] = (e[p] * invs + EPS_F) * wv[s];
            if (write_dots) g_inst_dots[dbase + (size_t)sp * NN] = dv[p];
            float sv = warp_sum(at[sp]);
            if (l == 0) atomicAdd(&g_inst_rowsum[b * 32 + sp], sv);
        }
    }

    __syncthreads();
#pragma unroll
    for (int i = 0; i < 32; i++) qs[i * 256 + t] = at[i];
    __syncthreads();

    float acc2[32];
#pragma unroll
    for (int i = 0; i < 32; i++) acc2[i] = 0.f;
    const float* vp = g_v + ((size_t)b * NN + n0) * DD + t;
#pragma unroll 1
    for (int nn = 0; nn < 256; nn += 4) {
        float v0 = vp[(size_t)(nn + 0) * DD];
        float v1 = vp[(size_t)(nn + 1) * DD];
        float v2 = vp[(size_t)(nn + 2) * DD];
        float v3 = vp[(size_t)(nn + 3) * DD];
#pragma unroll
        for (int i = 0; i < 32; i++) {
            float4 a4 = *(const float4*)&qs[i * 256 + nn];
            acc2[i] += v0 * a4.x + v1 * a4.y + v2 * a4.z + v3 * a4.w;
        }
    }
#pragma unroll
    for (int i = 0; i < 32; i++)
        atomicAdd(&g_inst_acc[(size_t)(b * 32 + i) * DD + t], acc2[i]);
}

// ---------------- 8) assemble output ----------------
__global__ void __launch_bounds__(256) write_out_kernel(float* __restrict__ out) {
    size_t idx = (size_t)blockIdx.x * 256 + threadIdx.x;
    const size_t A1 = 32768;
    const size_t A2 = 557056;
    const size_t A3 = 688128;
    const size_t A4 = 2785280;
    if (idx >= A4) return;
    float v;
    if (idx < A1)      v = g_sem_slots[idx];
    else if (idx < A2) v = g_sem_dots[idx - A1];
    else if (idx < A3) v = g_inst_slots[idx - A2];
    else               v = g_inst_dots[idx - A3];
    out[idx] = v;
}

// ---------------- launch ----------------
extern "C" void kernel_launch(void* const* d_in, const int* in_sizes, int n_in,
                              void* d_out, int out_size) {
    (void)in_sizes; (void)n_in; (void)out_size;
    const float* inputs      = (const float*)d_in[0];
    const float* noise       = (const float*)d_in[3];
    const float* ln_in_g     = (const float*)d_in[4];
    const float* ln_in_b     = (const float*)d_in[5];
    const float* ln_s_g      = (const float*)d_in[6];
    const float* ln_s_b      = (const float*)d_in[7];
    const float* ln_ff_g     = (const float*)d_in[8];
    const float* ln_ff_b     = (const float*)d_in[9];
    const float* slots_mu    = (const float*)d_in[10];
    const float* slots_sigma = (const float*)d_in[11];
    const float* Wq          = (const float*)d_in[12];
    const float* bq          = (const float*)d_in[13];
    const float* Wk          = (const float*)d_in[14];
    const float* bk          = (const float*)d_in[15];
    const float* Wv          = (const float*)d_in[16];
    const float* bv          = (const float*)d_in[17];
    const float* W1          = (const float*)d_in[18];
    const float* b1          = (const float*)d_in[19];
    const float* W2          = (const float*)d_in[20];
    const float* b2          = (const float*)d_in[21];
    float* out = (float*)d_out;

    const int sem_smem  = (NSL * 256 + 256 * KT_PITCH) * 4;   // 45,056 B
    const int inst_smem = (32 * 256 + 256 * KT_PITCH) * 4;    // 69,632 B
    static int attr_done = 0;
    if (!attr_done) {
        cudaFuncSetAttribute(sem_fused_kernel,  cudaFuncAttributeMaxDynamicSharedMemorySize, sem_smem);
        cudaFuncSetAttribute(inst_fused_kernel, cudaFuncAttributeMaxDynamicSharedMemorySize, inst_smem);
        attr_done = 1;
    }

    ln_input_kernel<<<BB * NN, 256>>>(inputs, ln_in_g, ln_in_b);

    dim3 gemm_grid(4, 512);
    gemm_tf32_kernel<<<gemm_grid, 256>>>(Wk, bk, Wv, bv);

    sem_init_kernel<<<BB * NSL, 256>>>(slots_mu);

    dim3 bn_grid(16, 16);
    for (int it = 0; it < 3; it++) {
        sem_q_kernel<<<BB * NSL / 4, 256>>>(ln_s_g, ln_s_b, Wq, bq);
        sem_fused_kernel<<<bn_grid, 256, sem_smem>>>(it == 2 ? 1 : 0);
        sem_mlp_kernel<<<BB * NSL / 4, 256>>>(ln_ff_g, ln_ff_b, W1, b1, W2, b2);
    }

    inst_init_kernel<<<BB * NSL * NPI, 256>>>(slots_mu, slots_sigma, noise);

    for (int it = 0; it < 3; it++) {
        inst_q_kernel<<<BB * NSL * NPI / 4, 256>>>(ln_s_g, ln_s_b, Wq, bq);
        inst_fused_kernel<<<bn_grid, 256, inst_smem>>>(it == 2 ? 1 : 0);
        inst_mlp_kernel<<<BB * NSL * NPI / 4, 256>>>(ln_ff_g, ln_ff_b, W1, b1, W2, b2);
    }

    write_out_kernel<<<10880, 256>>>(out);
}

// round 4
// speedup vs baseline: 1.6216x; 1.1595x over previous
#include <cuda_runtime.h>
#include <math.h>
#include <stdint.h>

#define BB   16
#define NN   4096
#define DD   256
#define NSL  8
#define NPI  4
#define HH   256
#define SCALE_F 0.0625f
#define EPS_F   1e-8f

#define KT_PITCH 36   // 32 floats + 4 pad

// ---------------- scratch ----------------
__device__ float g_x[BB*NN*DD];
__device__ float g_k[BB*NN*DD];
__device__ float g_v[BB*NN*DD];

__device__ float g_sem_slots[BB*NSL*DD];
__device__ float g_sem_q[BB*NSL*DD];
__device__ float g_sem_dots[BB*NSL*NN];
__device__ float g_sem_rowsum[BB*NSL];
__device__ float g_sem_acc[BB*NSL*DD];

__device__ float g_inst_slots[BB*NSL*NPI*DD];
__device__ float g_inst_q[BB*NSL*NPI*DD];
__device__ float g_inst_dots[BB*NSL*NPI*NN];
__device__ float g_inst_rowsum[BB*NSL*NPI];
__device__ float g_inst_acc[BB*NSL*NPI*DD];

// ---------------- helpers ----------------
__device__ __forceinline__ float warp_sum(float v) {
#pragma unroll
    for (int o = 16; o; o >>= 1) v += __shfl_xor_sync(0xffffffffu, v, o);
    return v;
}

__device__ __forceinline__ void block_stats(float v, float* rs, float* rs2, int t,
                                            float& m, float& inv) {
    float s  = warp_sum(v);
    float s2 = warp_sum(v * v);
    if ((t & 31) == 0) { rs[t >> 5] = s; rs2[t >> 5] = s2; }
    __syncthreads();
    float sum = 0.f, sum2 = 0.f;
#pragma unroll
    for (int i = 0; i < 8; i++) { sum += rs[i]; sum2 += rs2[i]; }
    m = sum * (1.0f / 256.0f);
    float var = sum2 * (1.0f / 256.0f) - m * m;
    inv = rsqrtf(var + 1e-5f);
    __syncthreads();
}

__device__ __forceinline__ uint32_t f2tf(float f) {
    uint32_t u;
    asm("cvt.rna.tf32.f32 %0, %1;" : "=r"(u) : "f"(f));
    return u;
}

__device__ __forceinline__ void mma_tf32(float* c, const uint32_t* a, const uint32_t* b) {
    asm volatile("mma.sync.aligned.m16n8k8.row.col.f32.tf32.tf32.f32 "
        "{%0,%1,%2,%3}, {%4,%5,%6,%7}, {%8,%9}, {%0,%1,%2,%3};"
        : "+f"(c[0]), "+f"(c[1]), "+f"(c[2]), "+f"(c[3])
        : "r"(a[0]), "r"(a[1]), "r"(a[2]), "r"(a[3]), "r"(b[0]), "r"(b[1]));
}

// ---------------- 1) LN over inputs ----------------
__global__ void __launch_bounds__(256) ln_input_kernel(const float* __restrict__ x,
                                                       const float* __restrict__ g,
                                                       const float* __restrict__ b) {
    __shared__ float rs[8], rs2[8];
    int row = blockIdx.x;
    int t   = threadIdx.x;
    float v = x[(size_t)row * DD + t];
    float m, inv;
    block_stats(v, rs, rs2, t, m, inv);
    g_x[(size_t)row * DD + t] = (v - m) * inv * g[t] + b[t];
}

// ---------------- 2) TF32 GEMM: {g_k,g_v}[M,256] = g_x @ {Wk,Wv} + bias ----------------
__global__ void __launch_bounds__(256) gemm_tf32_kernel(const float* __restrict__ Wk,
                                                        const float* __restrict__ bk,
                                                        const float* __restrict__ Wv,
                                                        const float* __restrict__ bv) {
    __shared__ uint32_t As[32][136];
    __shared__ uint32_t Bs[32][136];

    int t = threadIdx.x;
    int mat = blockIdx.x >> 1;
    const float* W    = mat ? Wv : Wk;
    const float* bias = mat ? bv : bk;
    float* C          = mat ? g_v : g_k;
    int nbase = (blockIdx.x & 1) * 128;
    size_t mbase = (size_t)blockIdx.y * 128;

    int wid = t >> 5, lane = t & 31;
    int wm = (wid >> 1) * 32;
    int wn = (wid & 1) * 64;
    int qrow = lane >> 2;
    int qk   = lane & 3;

    float c[2][8][4];
#pragma unroll
    for (int mt = 0; mt < 2; mt++)
#pragma unroll
        for (int nt = 0; nt < 8; nt++)
#pragma unroll
            for (int i = 0; i < 4; i++) c[mt][nt][i] = 0.f;

    int am  = t >> 1;
    int akc = (t & 1) * 16;
    const float* ap = g_x + (mbase + am) * 256 + akc;
    int bkr = t >> 3;
    int bn0 = (t & 7) * 16;
    const float* wp = W + (size_t)bkr * 256 + nbase + bn0;

    for (int k0 = 0; k0 < 256; k0 += 32) {
        __syncthreads();
#pragma unroll
        for (int j = 0; j < 4; j++) {
            float4 va = *(const float4*)(ap + k0 + j * 4);
            As[akc + j*4 + 0][am] = f2tf(va.x);
            As[akc + j*4 + 1][am] = f2tf(va.y);
            As[akc + j*4 + 2][am] = f2tf(va.z);
            As[akc + j*4 + 3][am] = f2tf(va.w);
            float4 vb = *(const float4*)(wp + (size_t)k0 * 256 + j * 4);
            Bs[bkr][bn0 + j*4 + 0] = f2tf(vb.x);
            Bs[bkr][bn0 + j*4 + 1] = f2tf(vb.y);
            Bs[bkr][bn0 + j*4 + 2] = f2tf(vb.z);
            Bs[bkr][bn0 + j*4 + 3] = f2tf(vb.w);
        }
        __syncthreads();

#pragma unroll
        for (int ks = 0; ks < 4; ks++) {
            int kb = ks * 8;
            uint32_t a[2][4], b[8][2];
#pragma unroll
            for (int mt = 0; mt < 2; mt++) {
                int m = wm + mt * 16 + qrow;
                a[mt][0] = As[kb + qk][m];
                a[mt][1] = As[kb + qk][m + 8];
                a[mt][2] = As[kb + qk + 4][m];
                a[mt][3] = As[kb + qk + 4][m + 8];
            }
#pragma unroll
            for (int nt = 0; nt < 8; nt++) {
                int n = wn + nt * 8 + qrow;
                b[nt][0] = Bs[kb + qk][n];
                b[nt][1] = Bs[kb + qk + 4][n];
            }
#pragma unroll
            for (int mt = 0; mt < 2; mt++)
#pragma unroll
                for (int nt = 0; nt < 8; nt++)
                    mma_tf32(c[mt][nt], a[mt], b[nt]);
        }
    }

#pragma unroll
    for (int mt = 0; mt < 2; mt++) {
        int r0 = wm + mt * 16 + qrow;
#pragma unroll
        for (int nt = 0; nt < 8; nt++) {
            int col = nbase + wn + nt * 8 + 2 * qk;
            float b0v = bias[col], b1v = bias[col + 1];
            size_t base0 = (mbase + r0) * 256 + col;
            size_t base1 = (mbase + r0 + 8) * 256 + col;
            *(float2*)(C + base0) = make_float2(c[mt][nt][0] + b0v, c[mt][nt][1] + b1v);
            *(float2*)(C + base1) = make_float2(c[mt][nt][2] + b0v, c[mt][nt][3] + b1v);
        }
    }
}

// ---------------- 3) init kernels ----------------
__global__ void sem_init_kernel(const float* __restrict__ mu) {
    int r = blockIdx.x;
    int i = r & 7;
    g_sem_slots[(size_t)r * DD + threadIdx.x] = mu[i * DD + threadIdx.x];
}

__global__ void inst_init_kernel(const float* __restrict__ mu,
                                 const float* __restrict__ sigma,
                                 const float* __restrict__ noise) {
    size_t idx = (size_t)blockIdx.x * 256 + threadIdx.x;
    int d = idx & 255;
    int s = (idx >> 10) & 7;
    g_inst_slots[idx] = mu[s * DD + d] + expf(sigma[s * DD + d]) * noise[idx];
}

// ---------------- 4) staged GEMV: out[r] = sum_d in[r][d] * W[d][t], 4 rows ----------------
__device__ __forceinline__ void gemm4_staged(const float* __restrict__ W,
                                             const float (*__restrict__ in)[DD],
                                             float (*__restrict__ ws)[DD],
                                             float* o, int t) {
    o[0] = o[1] = o[2] = o[3] = 0.f;
#pragma unroll 1
    for (int d0 = 0; d0 < DD; d0 += 16) {
        __syncthreads();
#pragma unroll
        for (int j = 0; j < 4; j++) {
            int idx = (t + j * 256) * 4;        // 0..4095 floats
            int r = idx >> 8, c = idx & 255;
            *(float4*)&ws[r][c] = *(const float4*)(W + (size_t)(d0 + r) * DD + c);
        }
        __syncthreads();
#pragma unroll
        for (int j4 = 0; j4 < 16; j4 += 4) {
            float w0 = ws[j4 + 0][t];
            float w1 = ws[j4 + 1][t];
            float w2 = ws[j4 + 2][t];
            float w3 = ws[j4 + 3][t];
#pragma unroll
            for (int r = 0; r < 4; r++) {
                float4 sv = *(const float4*)&in[r][d0 + j4];
                o[r] += sv.x * w0 + sv.y * w1 + sv.z * w2 + sv.w * w3;
            }
        }
    }
}

// ---------------- 5) fused MLP (iter t) + Q (iter t+1) + zero acc/rowsum ----------------
// which: 0 = sem arrays, 1 = inst arrays. Block = 4 slot rows, 256 threads.
template<bool DO_MLP, bool DO_Q>
__global__ void __launch_bounds__(256) mlpq_kernel(
    int which,
    const float* __restrict__ lnff_g, const float* __restrict__ lnff_b,
    const float* __restrict__ W1, const float* __restrict__ b1,
    const float* __restrict__ W2, const float* __restrict__ b2,
    const float* __restrict__ lns_g, const float* __restrict__ lns_b,
    const float* __restrict__ Wq, const float* __restrict__ bq)
{
    __shared__ float s1[4][DD];
    __shared__ float sln[4][DD];
    __shared__ float hs[4][DD];
    __shared__ float ws[16][DD];
    __shared__ float rs[8], rs2[8];

    float* slots  = which ? g_inst_slots  : g_sem_slots;
    float* q      = which ? g_inst_q      : g_sem_q;
    float* acc    = which ? g_inst_acc    : g_sem_acc;
    float* rowsum = which ? g_inst_rowsum : g_sem_rowsum;

    int t  = threadIdx.x;
    int r0 = blockIdx.x * 4;

    if (DO_MLP) {
        float gg = lnff_g[t], bb = lnff_b[t];
#pragma unroll
        for (int r = 0; r < 4; r++) {
            int row = r0 + r;
            float v = slots[(size_t)row * DD + t] + acc[(size_t)row * DD + t] / rowsum[row];
            s1[r][t] = v;
            float m, inv;
            block_stats(v, rs, rs2, t, m, inv);
            sln[r][t] = (v - m) * inv * gg + bb;
        }
        float h[4];
        gemm4_staged(W1, sln, ws, h, t);
        float b1v = b1[t];
#pragma unroll
        for (int r = 0; r < 4; r++) hs[r][t] = fmaxf(h[r] + b1v, 0.f);
        float o[4];
        gemm4_staged(W2, hs, ws, o, t);
        float b2v = b2[t];
#pragma unroll
        for (int r = 0; r < 4; r++) {
            float nv = s1[r][t] + o[r] + b2v;
            slots[(size_t)(r0 + r) * DD + t] = nv;
            s1[r][t] = nv;
        }
    } else {
#pragma unroll
        for (int r = 0; r < 4; r++) s1[r][t] = slots[(size_t)(r0 + r) * DD + t];
    }

    if (DO_Q) {
        float gg = lns_g[t], bb = lns_b[t];
#pragma unroll
        for (int r = 0; r < 4; r++) {
            int row = r0 + r;
            float v = s1[r][t];
            float m, inv;
            block_stats(v, rs, rs2, t, m, inv);
            sln[r][t] = (v - m) * inv * gg + bb;
            acc[(size_t)row * DD + t] = 0.f;
            if (t == 0) rowsum[row] = 0.f;
        }
        float qa[4];
        gemm4_staged(Wq, sln, ws, qa, t);
        float qb = bq[t];
#pragma unroll
        for (int r = 0; r < 4; r++)
            q[(size_t)(r0 + r) * DD + t] = qa[r] + qb;
    }
}

// ---------------- k-tile staged dots accumulation ----------------
template<int NR>
__device__ __forceinline__ void dots_accum(const float* __restrict__ kbase,
                                           const float* __restrict__ qs,
                                           float* __restrict__ kt,
                                           float* acc, int t) {
#pragma unroll 1
    for (int dt = 0; dt < DD; dt += 32) {
        __syncthreads();
#pragma unroll
        for (int j = 0; j < 8; j++) {
            int idx = t + j * 256;
            int row = idx >> 3;
            int c   = (idx & 7) * 4;
            float4 kv = *(const float4*)(kbase + (size_t)row * DD + dt + c);
            *(float4*)&kt[row * KT_PITCH + c] = kv;
        }
        __syncthreads();
#pragma unroll
        for (int d0 = 0; d0 < 32; d0 += 4) {
            float4 kv = *(const float4*)&kt[t * KT_PITCH + d0];
#pragma unroll
            for (int i = 0; i < NR; i++) {
                float4 qv = *(const float4*)&qs[i * 256 + dt + d0];
                acc[i] += kv.x * qv.x + kv.y * qv.y + kv.z * qv.z + kv.w * qv.w;
            }
        }
    }
}

// ---------------- 6) fused sem: dots + softmax(slots) + rowsum + update ----------------
__global__ void __launch_bounds__(256) sem_fused_kernel(int write_dots) {
    extern __shared__ float smem[];
    float* qs = smem;
    float* kt = smem + NSL * 256;

    int b  = blockIdx.y;
    int n0 = blockIdx.x * 256;
    int t  = threadIdx.x;
    int n  = n0 + t;

    for (int idx = t; idx < NSL * DD; idx += 256)
        qs[idx] = g_sem_q[(size_t)b * NSL * DD + idx];

    float acc[NSL];
#pragma unroll
    for (int i = 0; i < NSL; i++) acc[i] = 0.f;

    dots_accum<NSL>(g_k + ((size_t)b * NN + n0) * DD, qs, kt, acc, t);

    float dv[NSL], e[NSL];
    float mx = -1e30f;
#pragma unroll
    for (int i = 0; i < NSL; i++) { dv[i] = acc[i] * SCALE_F; mx = fmaxf(mx, dv[i]); }
    float ssum = 0.f;
#pragma unroll
    for (int i = 0; i < NSL; i++) { e[i] = expf(dv[i] - mx); ssum += e[i]; }
    float inv = 1.0f / ssum;

    size_t base = (size_t)b * NSL * NN + n;
    int l = t & 31;
    float at[NSL];
#pragma unroll
    for (int i = 0; i < NSL; i++) {
        at[i] = e[i] * inv + EPS_F;
        if (write_dots) g_sem_dots[base + (size_t)i * NN] = dv[i];
        float sv = warp_sum(at[i]);
        if (l == 0) atomicAdd(&g_sem_rowsum[b * NSL + i], sv);
    }

    __syncthreads();
#pragma unroll
    for (int i = 0; i < NSL; i++) qs[i * 256 + t] = at[i];
    __syncthreads();

    float acc2[NSL];
#pragma unroll
    for (int i = 0; i < NSL; i++) acc2[i] = 0.f;
    const float* vp = g_v + ((size_t)b * NN + n0) * DD + t;
#pragma unroll 1
    for (int nn = 0; nn < 256; nn += 4) {
        float v0 = vp[(size_t)(nn + 0) * DD];
        float v1 = vp[(size_t)(nn + 1) * DD];
        float v2 = vp[(size_t)(nn + 2) * DD];
        float v3 = vp[(size_t)(nn + 3) * DD];
#pragma unroll
        for (int i = 0; i < NSL; i++) {
            float4 a4 = *(const float4*)&qs[i * 256 + nn];
            acc2[i] += v0 * a4.x + v1 * a4.y + v2 * a4.z + v3 * a4.w;
        }
    }
#pragma unroll
    for (int i = 0; i < NSL; i++)
        atomicAdd(&g_sem_acc[(size_t)(b * NSL + i) * DD + t], acc2[i]);
}

// ---------------- 7) fused inst: dots + softmax(NP)*sem_w + rowsum + update ----------------
__global__ void __launch_bounds__(256) inst_fused_kernel(int write_dots) {
    extern __shared__ float smem[];
    float* qs = smem;
    float* kt = smem + 32 * 256;

    int b  = blockIdx.y;
    int n0 = blockIdx.x * 256;
    int t  = threadIdx.x;
    int n  = n0 + t;

    for (int idx = t; idx < 32 * DD; idx += 256)
        qs[idx] = g_inst_q[(size_t)b * 32 * DD + idx];

    float acc[32];
#pragma unroll
    for (int i = 0; i < 32; i++) acc[i] = 0.f;

    dots_accum<32>(g_k + ((size_t)b * NN + n0) * DD, qs, kt, acc, t);

    float wv[NSL];
    {
        size_t sbase = (size_t)b * NSL * NN + n;
        float sdv[NSL];
        float smx = -1e30f;
#pragma unroll
        for (int i = 0; i < NSL; i++) { sdv[i] = g_sem_dots[sbase + (size_t)i * NN]; smx = fmaxf(smx, sdv[i]); }
        float ss = 0.f;
#pragma unroll
        for (int i = 0; i < NSL; i++) { sdv[i] = expf(sdv[i] - smx); ss += sdv[i]; }
        float sinv = 1.0f / ss;
#pragma unroll
        for (int i = 0; i < NSL; i++) wv[i] = sdv[i] * sinv;
    }

    size_t dbase = (size_t)b * 32 * NN + n;
    int l = t & 31;
    float at[32];
#pragma unroll
    for (int s = 0; s < 8; s++) {
        float dv[NPI], e[NPI];
        float mx = -1e30f;
#pragma unroll
        for (int p = 0; p < NPI; p++) { dv[p] = acc[s * 4 + p] * SCALE_F; mx = fmaxf(mx, dv[p]); }
        float ssum = 0.f;
#pragma unroll
        for (int p = 0; p < NPI; p++) { e[p] = expf(dv[p] - mx); ssum += e[p]; }
        float invs = 1.0f / ssum;
#pragma unroll
        for (int p = 0; p < NPI; p++) {
            int sp = s * 4 + p;
            at[sp] = (e[p] * invs + EPS_F) * wv[s];
            if (write_dots) g_inst_dots[dbase + (size_t)sp * NN] = dv[p];
            float sv = warp_sum(at[sp]);
            if (l == 0) atomicAdd(&g_inst_rowsum[b * 32 + sp], sv);
        }
    }

    __syncthreads();
#pragma unroll
    for (int i = 0; i < 32; i++) qs[i * 256 + t] = at[i];
    __syncthreads();

    float acc2[32];
#pragma unroll
    for (int i = 0; i < 32; i++) acc2[i] = 0.f;
    const float* vp = g_v + ((size_t)b * NN + n0) * DD + t;
#pragma unroll 1
    for (int nn = 0; nn < 256; nn += 4) {
        float v0 = vp[(size_t)(nn + 0) * DD];
        float v1 = vp[(size_t)(nn + 1) * DD];
        float v2 = vp[(size_t)(nn + 2) * DD];
        float v3 = vp[(size_t)(nn + 3) * DD];
#pragma unroll
        for (int i = 0; i < 32; i++) {
            float4 a4 = *(const float4*)&qs[i * 256 + nn];
            acc2[i] += v0 * a4.x + v1 * a4.y + v2 * a4.z + v3 * a4.w;
        }
    }
#pragma unroll
    for (int i = 0; i < 32; i++)
        atomicAdd(&g_inst_acc[(size_t)(b * 32 + i) * DD + t], acc2[i]);
}

// ---------------- 8) assemble output ----------------
__global__ void __launch_bounds__(256) write_out_kernel(float* __restrict__ out) {
    size_t idx = (size_t)blockIdx.x * 256 + threadIdx.x;
    const size_t A1 = 32768;
    const size_t A2 = 557056;
    const size_t A3 = 688128;
    const size_t A4 = 2785280;
    if (idx >= A4) return;
    float v;
    if (idx < A1)      v = g_sem_slots[idx];
    else if (idx < A2) v = g_sem_dots[idx - A1];
    else if (idx < A3) v = g_inst_slots[idx - A2];
    else               v = g_inst_dots[idx - A3];
    out[idx] = v;
}

// ---------------- launch ----------------
extern "C" void kernel_launch(void* const* d_in, const int* in_sizes, int n_in,
                              void* d_out, int out_size) {
    (void)in_sizes; (void)n_in; (void)out_size;
    const float* inputs      = (const float*)d_in[0];
    const float* noise       = (const float*)d_in[3];
    const float* ln_in_g     = (const float*)d_in[4];
    const float* ln_in_b     = (const float*)d_in[5];
    const float* ln_s_g      = (const float*)d_in[6];
    const float* ln_s_b      = (const float*)d_in[7];
    const float* ln_ff_g     = (const float*)d_in[8];
    const float* ln_ff_b     = (const float*)d_in[9];
    const float* slots_mu    = (const float*)d_in[10];
    const float* slots_sigma = (const float*)d_in[11];
    const float* Wq          = (const float*)d_in[12];
    const float* bq          = (const float*)d_in[13];
    const float* Wk          = (const float*)d_in[14];
    const float* bk          = (const float*)d_in[15];
    const float* Wv          = (const float*)d_in[16];
    const float* bv          = (const float*)d_in[17];
    const float* W1          = (const float*)d_in[18];
    const float* b1          = (const float*)d_in[19];
    const float* W2          = (const float*)d_in[20];
    const float* b2          = (const float*)d_in[21];
    float* out = (float*)d_out;

    const int sem_smem  = (NSL * 256 + 256 * KT_PITCH) * 4;
    const int inst_smem = (32 * 256 + 256 * KT_PITCH) * 4;
    static int attr_done = 0;
    if (!attr_done) {
        cudaFuncSetAttribute(sem_fused_kernel,  cudaFuncAttributeMaxDynamicSharedMemorySize, sem_smem);
        cudaFuncSetAttribute(inst_fused_kernel, cudaFuncAttributeMaxDynamicSharedMemorySize, inst_smem);
        attr_done = 1;
    }

    ln_input_kernel<<<BB * NN, 256>>>(inputs, ln_in_g, ln_in_b);

    dim3 gemm_grid(4, 512);
    gemm_tf32_kernel<<<gemm_grid, 256>>>(Wk, bk, Wv, bv);

    sem_init_kernel<<<BB * NSL, 256>>>(slots_mu);

    dim3 bn_grid(16, 16);
    const int SEM_BLKS  = BB * NSL / 4;        // 32
    const int INST_BLKS = BB * NSL * NPI / 4;  // 128

    // q for iter 0 (+ zero)
    mlpq_kernel<false, true><<<SEM_BLKS, 256>>>(0, ln_ff_g, ln_ff_b, W1, b1, W2, b2,
                                                ln_s_g, ln_s_b, Wq, bq);
    for (int it = 0; it < 3; it++) {
        sem_fused_kernel<<<bn_grid, 256, sem_smem>>>(it == 2 ? 1 : 0);
        if (it < 2)
            mlpq_kernel<true, true><<<SEM_BLKS, 256>>>(0, ln_ff_g, ln_ff_b, W1, b1, W2, b2,
                                                       ln_s_g, ln_s_b, Wq, bq);
        else
            mlpq_kernel<true, false><<<SEM_BLKS, 256>>>(0, ln_ff_g, ln_ff_b, W1, b1, W2, b2,
                                                        ln_s_g, ln_s_b, Wq, bq);
    }

    inst_init_kernel<<<BB * NSL * NPI, 256>>>(slots_mu, slots_sigma, noise);

    mlpq_kernel<false, true><<<INST_BLKS, 256>>>(1, ln_ff_g, ln_ff_b, W1, b1, W2, b2,
                                                 ln_s_g, ln_s_b, Wq, bq);
    for (int it = 0; it < 3; it++) {
        inst_fused_kernel<<<bn_grid, 256, inst_smem>>>(it == 2 ? 1 : 0);
        if (it < 2)
            mlpq_kernel<true, true><<<INST_BLKS, 256>>>(1, ln_ff_g, ln_ff_b, W1, b1, W2, b2,
                                                        ln_s_g, ln_s_b, Wq, bq);
        else
            mlpq_kernel<true, false><<<INST_BLKS, 256>>>(1, ln_ff_g, ln_ff_b, W1, b1, W2, b2,
                                                         ln_s_g, ln_s_b, Wq, bq);
    }

    write_out_kernel<<<10880, 256>>>(out);
}

// round 5
// speedup vs baseline: 2.0910x; 1.2895x over previous
#include <cuda_runtime.h>
#include <math.h>
#include <stdint.h>

#define BB   16
#define NN   4096
#define DD   256
#define NSL  8
#define NPI  4
#define HH   256
#define SCALE_F 0.0625f
#define EPS_F   1e-8f

#define KTP 36    // k-tile pitch (tokens x 32d), 36%32=4 -> conflict-free b frags
#define PQ  260   // q/attn pitch (slots x 256),  260%32=4 -> conflict-free a frags
#define PV  264   // v-tile pitch (32 tok x 256d), 264%32=8 -> conflict-free b frags

// ---------------- scratch ----------------
__device__ float g_x[BB*NN*DD];
__device__ float g_k[BB*NN*DD];
__device__ float g_v[BB*NN*DD];

__device__ float g_sem_slots[BB*NSL*DD];
__device__ float g_sem_q[BB*NSL*DD];
__device__ float g_sem_dots[BB*NSL*NN];
__device__ float g_sem_rowsum[BB*NSL];
__device__ float g_sem_acc[BB*NSL*DD];

__device__ float g_inst_slots[BB*NSL*NPI*DD];
__device__ float g_inst_q[BB*NSL*NPI*DD];
__device__ float g_inst_dots[BB*NSL*NPI*NN];
__device__ float g_inst_rowsum[BB*NSL*NPI];
__device__ float g_inst_acc[BB*NSL*NPI*DD];

// ---------------- helpers ----------------
__device__ __forceinline__ float warp_sum(float v) {
#pragma unroll
    for (int o = 16; o; o >>= 1) v += __shfl_xor_sync(0xffffffffu, v, o);
    return v;
}

__device__ __forceinline__ void block_stats(float v, float* rs, float* rs2, int t,
                                            float& m, float& inv) {
    float s  = warp_sum(v);
    float s2 = warp_sum(v * v);
    if ((t & 31) == 0) { rs[t >> 5] = s; rs2[t >> 5] = s2; }
    __syncthreads();
    float sum = 0.f, sum2 = 0.f;
#pragma unroll
    for (int i = 0; i < 8; i++) { sum += rs[i]; sum2 += rs2[i]; }
    m = sum * (1.0f / 256.0f);
    float var = sum2 * (1.0f / 256.0f) - m * m;
    inv = rsqrtf(var + 1e-5f);
    __syncthreads();
}

__device__ __forceinline__ uint32_t f2tf(float f) {
    uint32_t u;
    asm("cvt.rna.tf32.f32 %0, %1;" : "=r"(u) : "f"(f));
    return u;
}

__device__ __forceinline__ void mma_tf32(float* c, const uint32_t* a, const uint32_t* b) {
    asm volatile("mma.sync.aligned.m16n8k8.row.col.f32.tf32.tf32.f32 "
        "{%0,%1,%2,%3}, {%4,%5,%6,%7}, {%8,%9}, {%0,%1,%2,%3};"
        : "+f"(c[0]), "+f"(c[1]), "+f"(c[2]), "+f"(c[3])
        : "r"(a[0]), "r"(a[1]), "r"(a[2]), "r"(a[3]), "r"(b[0]), "r"(b[1]));
}

// ---------------- 1) LN over inputs ----------------
__global__ void __launch_bounds__(256) ln_input_kernel(const float* __restrict__ x,
                                                       const float* __restrict__ g,
                                                       const float* __restrict__ b) {
    __shared__ float rs[8], rs2[8];
    int row = blockIdx.x;
    int t   = threadIdx.x;
    float v = x[(size_t)row * DD + t];
    float m, inv;
    block_stats(v, rs, rs2, t, m, inv);
    g_x[(size_t)row * DD + t] = (v - m) * inv * g[t] + b[t];
}

// ---------------- 2) TF32 GEMM: {g_k,g_v}[M,256] = g_x @ {Wk,Wv} + bias ----------------
__global__ void __launch_bounds__(256) gemm_tf32_kernel(const float* __restrict__ Wk,
                                                        const float* __restrict__ bk,
                                                        const float* __restrict__ Wv,
                                                        const float* __restrict__ bv) {
    __shared__ uint32_t As[32][136];
    __shared__ uint32_t Bs[32][136];

    int t = threadIdx.x;
    int mat = blockIdx.x >> 1;
    const float* W    = mat ? Wv : Wk;
    const float* bias = mat ? bv : bk;
    float* C          = mat ? g_v : g_k;
    int nbase = (blockIdx.x & 1) * 128;
    size_t mbase = (size_t)blockIdx.y * 128;

    int wid = t >> 5, lane = t & 31;
    int wm = (wid >> 1) * 32;
    int wn = (wid & 1) * 64;
    int qrow = lane >> 2;
    int qk   = lane & 3;

    float c[2][8][4];
#pragma unroll
    for (int mt = 0; mt < 2; mt++)
#pragma unroll
        for (int nt = 0; nt < 8; nt++)
#pragma unroll
            for (int i = 0; i < 4; i++) c[mt][nt][i] = 0.f;

    int am  = t >> 1;
    int akc = (t & 1) * 16;
    const float* ap = g_x + (mbase + am) * 256 + akc;
    int bkr = t >> 3;
    int bn0 = (t & 7) * 16;
    const float* wp = W + (size_t)bkr * 256 + nbase + bn0;

    for (int k0 = 0; k0 < 256; k0 += 32) {
        __syncthreads();
#pragma unroll
        for (int j = 0; j < 4; j++) {
            float4 va = *(const float4*)(ap + k0 + j * 4);
            As[akc + j*4 + 0][am] = f2tf(va.x);
            As[akc + j*4 + 1][am] = f2tf(va.y);
            As[akc + j*4 + 2][am] = f2tf(va.z);
            As[akc + j*4 + 3][am] = f2tf(va.w);
            float4 vb = *(const float4*)(wp + (size_t)k0 * 256 + j * 4);
            Bs[bkr][bn0 + j*4 + 0] = f2tf(vb.x);
            Bs[bkr][bn0 + j*4 + 1] = f2tf(vb.y);
            Bs[bkr][bn0 + j*4 + 2] = f2tf(vb.z);
            Bs[bkr][bn0 + j*4 + 3] = f2tf(vb.w);
        }
        __syncthreads();

#pragma unroll
        for (int ks = 0; ks < 4; ks++) {
            int kb = ks * 8;
            uint32_t a[2][4], b[8][2];
#pragma unroll
            for (int mt = 0; mt < 2; mt++) {
                int m = wm + mt * 16 + qrow;
                a[mt][0] = As[kb + qk][m];
                a[mt][1] = As[kb + qk][m + 8];
                a[mt][2] = As[kb + qk + 4][m];
                a[mt][3] = As[kb + qk + 4][m + 8];
            }
#pragma unroll
            for (int nt = 0; nt < 8; nt++) {
                int n = wn + nt * 8 + qrow;
                b[nt][0] = Bs[kb + qk][n];
                b[nt][1] = Bs[kb + qk + 4][n];
            }
#pragma unroll
            for (int mt = 0; mt < 2; mt++)
#pragma unroll
                for (int nt = 0; nt < 8; nt++)
                    mma_tf32(c[mt][nt], a[mt], b[nt]);
        }
    }

#pragma unroll
    for (int mt = 0; mt < 2; mt++) {
        int r0 = wm + mt * 16 + qrow;
#pragma unroll
        for (int nt = 0; nt < 8; nt++) {
            int col = nbase + wn + nt * 8 + 2 * qk;
            float b0v = bias[col], b1v = bias[col + 1];
            size_t base0 = (mbase + r0) * 256 + col;
            size_t base1 = (mbase + r0 + 8) * 256 + col;
            *(float2*)(C + base0) = make_float2(c[mt][nt][0] + b0v, c[mt][nt][1] + b1v);
            *(float2*)(C + base1) = make_float2(c[mt][nt][2] + b0v, c[mt][nt][3] + b1v);
        }
    }
}

// ---------------- 3) init kernels ----------------
__global__ void sem_init_kernel(const float* __restrict__ mu) {
    int r = blockIdx.x;
    int i = r & 7;
    g_sem_slots[(size_t)r * DD + threadIdx.x] = mu[i * DD + threadIdx.x];
}

__global__ void inst_init_kernel(const float* __restrict__ mu,
                                 const float* __restrict__ sigma,
                                 const float* __restrict__ noise) {
    size_t idx = (size_t)blockIdx.x * 256 + threadIdx.x;
    int d = idx & 255;
    int s = (idx >> 10) & 7;
    g_inst_slots[idx] = mu[s * DD + d] + expf(sigma[s * DD + d]) * noise[idx];
}

// ---------------- 4) pipelined staged GEMV (4 rows/block) ----------------
__device__ __forceinline__ void gemm4_staged(const float* __restrict__ W,
                                             const float (*__restrict__ in)[DD],
                                             float (*__restrict__ ws)[DD],
                                             float* o, int t) {
    o[0] = o[1] = o[2] = o[3] = 0.f;
    int r0 = t >> 6;
    int c0 = (t & 63) * 4;
    float4 pre[4];
#pragma unroll
    for (int j = 0; j < 4; j++)
        pre[j] = *(const float4*)(W + (size_t)(r0 + j * 4) * DD + c0);
#pragma unroll 1
    for (int d0 = 0; d0 < DD; d0 += 16) {
        __syncthreads();
#pragma unroll
        for (int j = 0; j < 4; j++)
            *(float4*)&ws[r0 + j * 4][c0] = pre[j];
        __syncthreads();
        if (d0 + 16 < DD) {
#pragma unroll
            for (int j = 0; j < 4; j++)
                pre[j] = *(const float4*)(W + (size_t)(d0 + 16 + r0 + j * 4) * DD + c0);
        }
#pragma unroll
        for (int j4 = 0; j4 < 16; j4 += 4) {
            float w0 = ws[j4 + 0][t];
            float w1 = ws[j4 + 1][t];
            float w2 = ws[j4 + 2][t];
            float w3 = ws[j4 + 3][t];
#pragma unroll
            for (int r = 0; r < 4; r++) {
                float4 sv = *(const float4*)&in[r][d0 + j4];
                o[r] += sv.x * w0 + sv.y * w1 + sv.z * w2 + sv.w * w3;
            }
        }
    }
}

// ---------------- 5) fused MLP + Q + zero ----------------
template<bool DO_MLP, bool DO_Q>
__global__ void __launch_bounds__(256) mlpq_kernel(
    int which,
    const float* __restrict__ lnff_g, const float* __restrict__ lnff_b,
    const float* __restrict__ W1, const float* __restrict__ b1,
    const float* __restrict__ W2, const float* __restrict__ b2,
    const float* __restrict__ lns_g, const float* __restrict__ lns_b,
    const float* __restrict__ Wq, const float* __restrict__ bq)
{
    __shared__ float s1[4][DD];
    __shared__ float sln[4][DD];
    __shared__ float hs[4][DD];
    __shared__ float ws[16][DD];
    __shared__ float rs[8], rs2[8];

    float* slots  = which ? g_inst_slots  : g_sem_slots;
    float* q      = which ? g_inst_q      : g_sem_q;
    float* acc    = which ? g_inst_acc    : g_sem_acc;
    float* rowsum = which ? g_inst_rowsum : g_sem_rowsum;

    int t  = threadIdx.x;
    int r0 = blockIdx.x * 4;

    if (DO_MLP) {
        float gg = lnff_g[t], bb = lnff_b[t];
#pragma unroll
        for (int r = 0; r < 4; r++) {
            int row = r0 + r;
            float v = slots[(size_t)row * DD + t] + acc[(size_t)row * DD + t] / rowsum[row];
            s1[r][t] = v;
            float m, inv;
            block_stats(v, rs, rs2, t, m, inv);
            sln[r][t] = (v - m) * inv * gg + bb;
        }
        float h[4];
        gemm4_staged(W1, sln, ws, h, t);
        float b1v = b1[t];
#pragma unroll
        for (int r = 0; r < 4; r++) hs[r][t] = fmaxf(h[r] + b1v, 0.f);
        float o[4];
        gemm4_staged(W2, hs, ws, o, t);
        float b2v = b2[t];
#pragma unroll
        for (int r = 0; r < 4; r++) {
            float nv = s1[r][t] + o[r] + b2v;
            slots[(size_t)(r0 + r) * DD + t] = nv;
            s1[r][t] = nv;
        }
    } else {
#pragma unroll
        for (int r = 0; r < 4; r++) s1[r][t] = slots[(size_t)(r0 + r) * DD + t];
    }

    if (DO_Q) {
        float gg = lns_g[t], bb = lns_b[t];
#pragma unroll
        for (int r = 0; r < 4; r++) {
            int row = r0 + r;
            float v = s1[r][t];
            float m, inv;
            block_stats(v, rs, rs2, t, m, inv);
            sln[r][t] = (v - m) * inv * gg + bb;
            acc[(size_t)row * DD + t] = 0.f;
            if (t == 0) rowsum[row] = 0.f;
        }
        float qa[4];
        gemm4_staged(Wq, sln, ws, qa, t);
        float qb = bq[t];
#pragma unroll
        for (int r = 0; r < 4; r++)
            q[(size_t)(r0 + r) * DD + t] = qa[r] + qb;
    }
}

// ---------------- mma phase helpers ----------------
// dots: D[slot][token] = q[slot][d] . k[token][d]; per-warp 32 tokens, MT m-tiles
template<int MT>
__device__ __forceinline__ void dots_phase(const float* __restrict__ kbase,
                                           const float* __restrict__ qs,
                                           float* __restrict__ kt,
                                           float c[MT][4][4], int t) {
    int lane = t & 31, wid = t >> 5;
    int qrow = lane >> 2, qk = lane & 3;
    int wn = wid * 32;
#pragma unroll
    for (int mt = 0; mt < MT; mt++)
#pragma unroll
        for (int nt = 0; nt < 4; nt++)
#pragma unroll
            for (int i = 0; i < 4; i++) c[mt][nt][i] = 0.f;

    const uint32_t* qsu = (const uint32_t*)qs;
    const uint32_t* ktu = (const uint32_t*)kt;

#pragma unroll 1
    for (int dc = 0; dc < DD; dc += 32) {
        __syncthreads();
#pragma unroll
        for (int j = 0; j < 8; j++) {
            int idx = t + j * 256;
            int row = idx >> 3;
            int c4  = (idx & 7) * 4;
            float4 kv = *(const float4*)(kbase + (size_t)row * DD + dc + c4);
            uint32_t* dst = (uint32_t*)&kt[row * KTP + c4];
            dst[0] = f2tf(kv.x); dst[1] = f2tf(kv.y);
            dst[2] = f2tf(kv.z); dst[3] = f2tf(kv.w);
        }
        __syncthreads();
#pragma unroll
        for (int k8 = 0; k8 < 4; k8++) {
            uint32_t a[MT][4], b[4][2];
            int kg = dc + k8 * 8 + qk;
            int kl = k8 * 8 + qk;
#pragma unroll
            for (int mt = 0; mt < MT; mt++) {
                int m0 = mt * 16 + qrow;
                a[mt][0] = qsu[m0 * PQ + kg];
                a[mt][1] = qsu[(m0 + 8) * PQ + kg];
                a[mt][2] = qsu[m0 * PQ + kg + 4];
                a[mt][3] = qsu[(m0 + 8) * PQ + kg + 4];
            }
#pragma unroll
            for (int nt = 0; nt < 4; nt++) {
                int n = wn + nt * 8 + qrow;
                b[nt][0] = ktu[n * KTP + kl];
                b[nt][1] = ktu[n * KTP + kl + 4];
            }
#pragma unroll
            for (int mt = 0; mt < MT; mt++)
#pragma unroll
                for (int nt = 0; nt < 4; nt++)
                    mma_tf32(c[mt][nt], a[mt], b[nt]);
        }
    }
}

template<int MT, int PD>
__device__ __forceinline__ void store_dots(float c[MT][4][4], float* __restrict__ dotm, int t) {
    int lane = t & 31, wid = t >> 5;
    int qrow = lane >> 2, qk = lane & 3;
    int wn = wid * 32;
#pragma unroll
    for (int mt = 0; mt < MT; mt++)
#pragma unroll
        for (int nt = 0; nt < 4; nt++) {
            int tok = wn + nt * 8 + 2 * qk;
            int m0  = mt * 16 + qrow;
            dotm[tok * PD + m0]           = c[mt][nt][0] * SCALE_F;
            dotm[(tok + 1) * PD + m0]     = c[mt][nt][1] * SCALE_F;
            dotm[tok * PD + m0 + 8]       = c[mt][nt][2] * SCALE_F;
            dotm[(tok + 1) * PD + m0 + 8] = c[mt][nt][3] * SCALE_F;
        }
}

// update: D[slot][d] = attn[slot][token] . v[token][d]; per-warp 32 d cols
template<int MT>
__device__ __forceinline__ void upd_phase(const float* __restrict__ vbase,
                                          const float* __restrict__ atm,
                                          float* __restrict__ vt,
                                          float c[MT][4][4], int t) {
    int lane = t & 31, wid = t >> 5;
    int qrow = lane >> 2, qk = lane & 3;
    int wd = wid * 32;
#pragma unroll
    for (int mt = 0; mt < MT; mt++)
#pragma unroll
        for (int nt = 0; nt < 4; nt++)
#pragma unroll
            for (int i = 0; i < 4; i++) c[mt][nt][i] = 0.f;

    const uint32_t* au = (const uint32_t*)atm;
    const uint32_t* vu = (const uint32_t*)vt;

#pragma unroll 1
    for (int tc = 0; tc < 256; tc += 32) {
        __syncthreads();
#pragma unroll
        for (int j = 0; j < 8; j++) {
            int idx = t + j * 256;
            int row = idx >> 6;          // 0..31 local token
            int c4  = (idx & 63) * 4;    // 0..252
            float4 vv = *(const float4*)(vbase + (size_t)(tc + row) * DD + c4);
            uint32_t* dst = (uint32_t*)&vt[row * PV + c4];
            dst[0] = f2tf(vv.x); dst[1] = f2tf(vv.y);
            dst[2] = f2tf(vv.z); dst[3] = f2tf(vv.w);
        }
        __syncthreads();
#pragma unroll
        for (int k8 = 0; k8 < 4; k8++) {
            uint32_t a[MT][4], b[4][2];
            int kg = tc + k8 * 8 + qk;   // global token within tile
            int kl = k8 * 8 + qk;        // local token in vt
#pragma unroll
            for (int mt = 0; mt < MT; mt++) {
                int m0 = mt * 16 + qrow;
                a[mt][0] = au[m0 * PQ + kg];
                a[mt][1] = au[(m0 + 8) * PQ + kg];
                a[mt][2] = au[m0 * PQ + kg + 4];
                a[mt][3] = au[(m0 + 8) * PQ + kg + 4];
            }
#pragma unroll
            for (int nt = 0; nt < 4; nt++) {
                int d = wd + nt * 8 + qrow;
                b[nt][0] = vu[kl * PV + d];
                b[nt][1] = vu[(kl + 4) * PV + d];
            }
#pragma unroll
            for (int mt = 0; mt < MT; mt++)
#pragma unroll
                for (int nt = 0; nt < 4; nt++)
                    mma_tf32(c[mt][nt], a[mt], b[nt]);
        }
    }
}

template<int MT, int NRS>
__device__ __forceinline__ void upd_atomics(float c[MT][4][4], float* __restrict__ gacc,
                                            int slot_base, int t) {
    int lane = t & 31, wid = t >> 5;
    int qrow = lane >> 2, qk = lane & 3;
    int wd = wid * 32;
#pragma unroll
    for (int mt = 0; mt < MT; mt++)
#pragma unroll
        for (int nt = 0; nt < 4; nt++) {
            int d  = wd + nt * 8 + 2 * qk;
            int s0 = mt * 16 + qrow;
            atomicAdd(&gacc[(size_t)(slot_base + s0) * DD + d],     c[mt][nt][0]);
            atomicAdd(&gacc[(size_t)(slot_base + s0) * DD + d + 1], c[mt][nt][1]);
            if (s0 + 8 < NRS) {
                atomicAdd(&gacc[(size_t)(slot_base + s0 + 8) * DD + d],     c[mt][nt][2]);
                atomicAdd(&gacc[(size_t)(slot_base + s0 + 8) * DD + d + 1], c[mt][nt][3]);
            }
        }
}

// ---------------- 6) fused sem (mma) ----------------
// smem: qs/atm [16][PQ] then shared region (kt / dotm / vt)
__global__ void __launch_bounds__(256) sem_fused_kernel(int write_dots) {
    extern __shared__ float smem[];
    float* qs  = smem;                  // 16*PQ (q, then attn)
    float* reg2 = smem + 16 * PQ;       // 9216 floats: kt / dotm / vt
    const int PD = 17;

    int b  = blockIdx.y;
    int n0 = blockIdx.x * 256;
    int t  = threadIdx.x;
    int n  = n0 + t;

    // stage q (tf32 bits), zero pad slots 8..15
    for (int idx = t; idx < NSL * DD; idx += 256) {
        int r = idx >> 8, cc = idx & 255;
        ((uint32_t*)qs)[r * PQ + cc] = f2tf(g_sem_q[(size_t)b * NSL * DD + idx]);
    }
    for (int idx = t; idx < 8 * DD; idx += 256) {
        int r = idx >> 8, cc = idx & 255;
        qs[(NSL + r) * PQ + cc] = 0.f;
    }

    float c[1][4][4];
    dots_phase<1>(g_k + ((size_t)b * NN + n0) * DD, qs, reg2, c, t);

    __syncthreads();                    // kt reads done
    store_dots<1, PD>(c, reg2, t);
    __syncthreads();

    // per-token softmax over 8 slots
    float dv[NSL], e[NSL];
    float mx = -1e30f;
#pragma unroll
    for (int i = 0; i < NSL; i++) { dv[i] = reg2[t * PD + i]; mx = fmaxf(mx, dv[i]); }
    float ssum = 0.f;
#pragma unroll
    for (int i = 0; i < NSL; i++) { e[i] = expf(dv[i] - mx); ssum += e[i]; }
    float inv = 1.0f / ssum;

    size_t base = (size_t)b * NSL * NN + n;
    int l = t & 31;
    float at[NSL];
#pragma unroll
    for (int i = 0; i < NSL; i++) {
        at[i] = e[i] * inv + EPS_F;
        if (write_dots) g_sem_dots[base + (size_t)i * NN] = dv[i];
        float sv = warp_sum(at[i]);
        if (l == 0) atomicAdd(&g_sem_rowsum[b * NSL + i], sv);
    }

    __syncthreads();                    // dotm reads done
#pragma unroll
    for (int i = 0; i < NSL; i++)
        ((uint32_t*)qs)[i * PQ + t] = f2tf(at[i]);
#pragma unroll
    for (int i = NSL; i < 16; i++)
        qs[i * PQ + t] = 0.f;
    __syncthreads();

    float c2[1][4][4];
    upd_phase<1>(g_v + ((size_t)b * NN + n0) * DD, qs, reg2, c2, t);
    upd_atomics<1, NSL>(c2, g_sem_acc, b * NSL, t);
}

// ---------------- 7) fused inst (mma) ----------------
__global__ void __launch_bounds__(256) inst_fused_kernel(int write_dots) {
    extern __shared__ float smem[];
    float* qs   = smem;                 // 32*PQ (q, then attn)
    float* reg2 = smem + 32 * PQ;       // 9216 floats: kt / dotm / vt
    const int PD = 33;

    int b  = blockIdx.y;
    int n0 = blockIdx.x * 256;
    int t  = threadIdx.x;
    int n  = n0 + t;

    for (int idx = t; idx < 32 * DD; idx += 256) {
        int r = idx >> 8, cc = idx & 255;
        ((uint32_t*)qs)[r * PQ + cc] = f2tf(g_inst_q[(size_t)b * 32 * DD + idx]);
    }

    float c[2][4][4];
    dots_phase<2>(g_k + ((size_t)b * NN + n0) * DD, qs, reg2, c, t);

    __syncthreads();
    store_dots<2, PD>(c, reg2, t);
    __syncthreads();

    // sem_w on the fly
    float wv[NSL];
    {
        size_t sbase = (size_t)b * NSL * NN + n;
        float sdv[NSL];
        float smx = -1e30f;
#pragma unroll
        for (int i = 0; i < NSL; i++) { sdv[i] = g_sem_dots[sbase + (size_t)i * NN]; smx = fmaxf(smx, sdv[i]); }
        float ss = 0.f;
#pragma unroll
        for (int i = 0; i < NSL; i++) { sdv[i] = expf(sdv[i] - smx); ss += sdv[i]; }
        float sinv = 1.0f / ss;
#pragma unroll
        for (int i = 0; i < NSL; i++) wv[i] = sdv[i] * sinv;
    }

    size_t dbase = (size_t)b * 32 * NN + n;
    int l = t & 31;
    float at[32];
#pragma unroll
    for (int s = 0; s < 8; s++) {
        float dv[NPI], e[NPI];
        float mx = -1e30f;
#pragma unroll
        for (int p = 0; p < NPI; p++) { dv[p] = reg2[t * PD + s * 4 + p]; mx = fmaxf(mx, dv[p]); }
        float ssum = 0.f;
#pragma unroll
        for (int p = 0; p < NPI; p++) { e[p] = expf(dv[p] - mx); ssum += e[p]; }
        float invs = 1.0f / ssum;
#pragma unroll
        for (int p = 0; p < NPI; p++) {
            int sp = s * 4 + p;
            at[sp] = (e[p] * invs + EPS_F) * wv[s];
            if (write_dots) g_inst_dots[dbase + (size_t)sp * NN] = dv[p];
            float sv = warp_sum(at[sp]);
            if (l == 0) atomicAdd(&g_inst_rowsum[b * 32 + sp], sv);
        }
    }

    __syncthreads();
#pragma unroll
    for (int i = 0; i < 32; i++)
        ((uint32_t*)qs)[i * PQ + t] = f2tf(at[i]);
    __syncthreads();

    float c2[2][4][4];
    upd_phase<2>(g_v + ((size_t)b * NN + n0) * DD, qs, reg2, c2, t);
    upd_atomics<2, 32>(c2, g_inst_acc, b * 32, t);
}

// ---------------- 8) assemble output ----------------
__global__ void __launch_bounds__(256) write_out_kernel(float* __restrict__ out) {
    size_t idx = (size_t)blockIdx.x * 256 + threadIdx.x;
    const size_t A1 = 32768;
    const size_t A2 = 557056;
    const size_t A3 = 688128;
    const size_t A4 = 2785280;
    if (idx >= A4) return;
    float v;
    if (idx < A1)      v = g_sem_slots[idx];
    else if (idx < A2) v = g_sem_dots[idx - A1];
    else if (idx < A3) v = g_inst_slots[idx - A2];
    else               v = g_inst_dots[idx - A3];
    out[idx] = v;
}

// ---------------- launch ----------------
extern "C" void kernel_launch(void* const* d_in, const int* in_sizes, int n_in,
                              void* d_out, int out_size) {
    (void)in_sizes; (void)n_in; (void)out_size;
    const float* inputs      = (const float*)d_in[0];
    const float* noise       = (const float*)d_in[3];
    const float* ln_in_g     = (const float*)d_in[4];
    const float* ln_in_b     = (const float*)d_in[5];
    const float* ln_s_g      = (const float*)d_in[6];
    const float* ln_s_b      = (const float*)d_in[7];
    const float* ln_ff_g     = (const float*)d_in[8];
    const float* ln_ff_b     = (const float*)d_in[9];
    const float* slots_mu    = (const float*)d_in[10];
    const float* slots_sigma = (const float*)d_in[11];
    const float* Wq          = (const float*)d_in[12];
    const float* bq          = (const float*)d_in[13];
    const float* Wk          = (const float*)d_in[14];
    const float* bk          = (const float*)d_in[15];
    const float* Wv          = (const float*)d_in[16];
    const float* bv          = (const float*)d_in[17];
    const float* W1          = (const float*)d_in[18];
    const float* b1          = (const float*)d_in[19];
    const float* W2          = (const float*)d_in[20];
    const float* b2          = (const float*)d_in[21];
    float* out = (float*)d_out;

    const int sem_smem  = (16 * PQ + 9216) * 4;   // 53,504 B
    const int inst_smem = (32 * PQ + 9216) * 4;   // 70,144 B
    static int attr_done = 0;
    if (!attr_done) {
        cudaFuncSetAttribute(sem_fused_kernel,  cudaFuncAttributeMaxDynamicSharedMemorySize, sem_smem);
        cudaFuncSetAttribute(inst_fused_kernel, cudaFuncAttributeMaxDynamicSharedMemorySize, inst_smem);
        attr_done = 1;
    }

    ln_input_kernel<<<BB * NN, 256>>>(inputs, ln_in_g, ln_in_b);

    dim3 gemm_grid(4, 512);
    gemm_tf32_kernel<<<gemm_grid, 256>>>(Wk, bk, Wv, bv);

    sem_init_kernel<<<BB * NSL, 256>>>(slots_mu);

    dim3 bn_grid(16, 16);
    const int SEM_BLKS  = BB * NSL / 4;        // 32
    const int INST_BLKS = BB * NSL * NPI / 4;  // 128

    mlpq_kernel<false, true><<<SEM_BLKS, 256>>>(0, ln_ff_g, ln_ff_b, W1, b1, W2, b2,
                                                ln_s_g, ln_s_b, Wq, bq);
    for (int it = 0; it < 3; it++) {
        sem_fused_kernel<<<bn_grid, 256, sem_smem>>>(it == 2 ? 1 : 0);
        if (it < 2)
            mlpq_kernel<true, true><<<SEM_BLKS, 256>>>(0, ln_ff_g, ln_ff_b, W1, b1, W2, b2,
                                                       ln_s_g, ln_s_b, Wq, bq);
        else
            mlpq_kernel<true, false><<<SEM_BLKS, 256>>>(0, ln_ff_g, ln_ff_b, W1, b1, W2, b2,
                                                        ln_s_g, ln_s_b, Wq, bq);
    }

    inst_init_kernel<<<BB * NSL * NPI, 256>>>(slots_mu, slots_sigma, noise);

    mlpq_kernel<false, true><<<INST_BLKS, 256>>>(1, ln_ff_g, ln_ff_b, W1, b1, W2, b2,
                                                 ln_s_g, ln_s_b, Wq, bq);
    for (int it = 0; it < 3; it++) {
        inst_fused_kernel<<<bn_grid, 256, inst_smem>>>(it == 2 ? 1 : 0);
        if (it < 2)
            mlpq_kernel<true, true><<<INST_BLKS, 256>>>(1, ln_ff_g, ln_ff_b, W1, b1, W2, b2,
                                                        ln_s_g, ln_s_b, Wq, bq);
        else
            mlpq_kernel<true, false><<<INST_BLKS, 256>>>(1, ln_ff_g, ln_ff_b, W1, b1, W2, b2,
                                                         ln_s_g, ln_s_b, Wq, bq);
    }

    write_out_kernel<<<10880, 256>>>(out);
}

// round 6
// speedup vs baseline: 2.4282x; 1.1613x over previous
#include <cuda_runtime.h>
#include <math.h>
#include <stdint.h>

#define BB   16
#define NN   4096
#define DD   256
#define NSL  8
#define NPI  4
#define HH   256
#define SCALE_F 0.0625f
#define EPS_F   1e-8f

#define KTP 36    // k-tile pitch
#define PQ  260   // q/attn pitch
#define PV  264   // v-tile pitch
#define RBUF 9216 // floats per staging buffer

// ---------------- scratch ----------------
__device__ float g_x[BB*NN*DD];
__device__ float g_k[BB*NN*DD];
__device__ float g_v[BB*NN*DD];

__device__ float g_sem_slots[BB*NSL*DD];
__device__ float g_sem_q[BB*NSL*DD];
__device__ float g_sem_dots[BB*NSL*NN];
__device__ float g_sem_rowsum[BB*NSL];
__device__ float g_sem_acc[BB*NSL*DD];

__device__ float g_inst_slots[BB*NSL*NPI*DD];
__device__ float g_inst_q[BB*NSL*NPI*DD];
__device__ float g_inst_dots[BB*NSL*NPI*NN];
__device__ float g_inst_rowsum[BB*NSL*NPI];
__device__ float g_inst_acc[BB*NSL*NPI*DD];

// ---------------- helpers ----------------
__device__ __forceinline__ float warp_sum(float v) {
#pragma unroll
    for (int o = 16; o; o >>= 1) v += __shfl_xor_sync(0xffffffffu, v, o);
    return v;
}

__device__ __forceinline__ void block_stats(float v, float* rs, float* rs2, int t,
                                            float& m, float& inv) {
    float s  = warp_sum(v);
    float s2 = warp_sum(v * v);
    if ((t & 31) == 0) { rs[t >> 5] = s; rs2[t >> 5] = s2; }
    __syncthreads();
    float sum = 0.f, sum2 = 0.f;
#pragma unroll
    for (int i = 0; i < 8; i++) { sum += rs[i]; sum2 += rs2[i]; }
    m = sum * (1.0f / 256.0f);
    float var = sum2 * (1.0f / 256.0f) - m * m;
    inv = rsqrtf(var + 1e-5f);
    __syncthreads();
}

__device__ __forceinline__ uint32_t f2tf(float f) {
    uint32_t u;
    asm("cvt.rna.tf32.f32 %0, %1;" : "=r"(u) : "f"(f));
    return u;
}

__device__ __forceinline__ void mma_tf32(float* c, const uint32_t* a, const uint32_t* b) {
    asm volatile("mma.sync.aligned.m16n8k8.row.col.f32.tf32.tf32.f32 "
        "{%0,%1,%2,%3}, {%4,%5,%6,%7}, {%8,%9}, {%0,%1,%2,%3};"
        : "+f"(c[0]), "+f"(c[1]), "+f"(c[2]), "+f"(c[3])
        : "r"(a[0]), "r"(a[1]), "r"(a[2]), "r"(a[3]), "r"(b[0]), "r"(b[1]));
}

// ---------------- 1) LN over inputs ----------------
__global__ void __launch_bounds__(256) ln_input_kernel(const float* __restrict__ x,
                                                       const float* __restrict__ g,
                                                       const float* __restrict__ b) {
    __shared__ float rs[8], rs2[8];
    int row = blockIdx.x;
    int t   = threadIdx.x;
    float v = x[(size_t)row * DD + t];
    float m, inv;
    block_stats(v, rs, rs2, t, m, inv);
    g_x[(size_t)row * DD + t] = (v - m) * inv * g[t] + b[t];
}

// ---------------- 2) TF32 GEMM: {g_k,g_v}[M,256] = g_x @ {Wk,Wv} + bias ----------------
__global__ void __launch_bounds__(256) gemm_tf32_kernel(const float* __restrict__ Wk,
                                                        const float* __restrict__ bk,
                                                        const float* __restrict__ Wv,
                                                        const float* __restrict__ bv) {
    __shared__ uint32_t As[32][136];
    __shared__ uint32_t Bs[32][136];

    int t = threadIdx.x;
    int mat = blockIdx.x >> 1;
    const float* W    = mat ? Wv : Wk;
    const float* bias = mat ? bv : bk;
    float* C          = mat ? g_v : g_k;
    int nbase = (blockIdx.x & 1) * 128;
    size_t mbase = (size_t)blockIdx.y * 128;

    int wid = t >> 5, lane = t & 31;
    int wm = (wid >> 1) * 32;
    int wn = (wid & 1) * 64;
    int qrow = lane >> 2;
    int qk   = lane & 3;

    float c[2][8][4];
#pragma unroll
    for (int mt = 0; mt < 2; mt++)
#pragma unroll
        for (int nt = 0; nt < 8; nt++)
#pragma unroll
            for (int i = 0; i < 4; i++) c[mt][nt][i] = 0.f;

    int am  = t >> 1;
    int akc = (t & 1) * 16;
    const float* ap = g_x + (mbase + am) * 256 + akc;
    int bkr = t >> 3;
    int bn0 = (t & 7) * 16;
    const float* wp = W + (size_t)bkr * 256 + nbase + bn0;

    for (int k0 = 0; k0 < 256; k0 += 32) {
        __syncthreads();
#pragma unroll
        for (int j = 0; j < 4; j++) {
            float4 va = *(const float4*)(ap + k0 + j * 4);
            As[akc + j*4 + 0][am] = f2tf(va.x);
            As[akc + j*4 + 1][am] = f2tf(va.y);
            As[akc + j*4 + 2][am] = f2tf(va.z);
            As[akc + j*4 + 3][am] = f2tf(va.w);
            float4 vb = *(const float4*)(wp + (size_t)k0 * 256 + j * 4);
            Bs[bkr][bn0 + j*4 + 0] = f2tf(vb.x);
            Bs[bkr][bn0 + j*4 + 1] = f2tf(vb.y);
            Bs[bkr][bn0 + j*4 + 2] = f2tf(vb.z);
            Bs[bkr][bn0 + j*4 + 3] = f2tf(vb.w);
        }
        __syncthreads();

#pragma unroll
        for (int ks = 0; ks < 4; ks++) {
            int kb = ks * 8;
            uint32_t a[2][4], b[8][2];
#pragma unroll
            for (int mt = 0; mt < 2; mt++) {
                int m = wm + mt * 16 + qrow;
                a[mt][0] = As[kb + qk][m];
                a[mt][1] = As[kb + qk][m + 8];
                a[mt][2] = As[kb + qk + 4][m];
                a[mt][3] = As[kb + qk + 4][m + 8];
            }
#pragma unroll
            for (int nt = 0; nt < 8; nt++) {
                int n = wn + nt * 8 + qrow;
                b[nt][0] = Bs[kb + qk][n];
                b[nt][1] = Bs[kb + qk + 4][n];
            }
#pragma unroll
            for (int mt = 0; mt < 2; mt++)
#pragma unroll
                for (int nt = 0; nt < 8; nt++)
                    mma_tf32(c[mt][nt], a[mt], b[nt]);
        }
    }

#pragma unroll
    for (int mt = 0; mt < 2; mt++) {
        int r0 = wm + mt * 16 + qrow;
#pragma unroll
        for (int nt = 0; nt < 8; nt++) {
            int col = nbase + wn + nt * 8 + 2 * qk;
            float b0v = bias[col], b1v = bias[col + 1];
            size_t base0 = (mbase + r0) * 256 + col;
            size_t base1 = (mbase + r0 + 8) * 256 + col;
            *(float2*)(C + base0) = make_float2(c[mt][nt][0] + b0v, c[mt][nt][1] + b1v);
            *(float2*)(C + base1) = make_float2(c[mt][nt][2] + b0v, c[mt][nt][3] + b1v);
        }
    }
}

// ---------------- 3) init kernels ----------------
__global__ void sem_init_kernel(const float* __restrict__ mu) {
    int r = blockIdx.x;
    int i = r & 7;
    g_sem_slots[(size_t)r * DD + threadIdx.x] = mu[i * DD + threadIdx.x];
}

__global__ void inst_init_kernel(const float* __restrict__ mu,
                                 const float* __restrict__ sigma,
                                 const float* __restrict__ noise) {
    size_t idx = (size_t)blockIdx.x * 256 + threadIdx.x;
    int d = idx & 255;
    int s = (idx >> 10) & 7;
    g_inst_slots[idx] = mu[s * DD + d] + expf(sigma[s * DD + d]) * noise[idx];
}

// ---------------- 4) double-buffered staged GEMV (4 rows/block) ----------------
__device__ __forceinline__ void gemm4_staged(const float* __restrict__ W,
                                             const float (*__restrict__ in)[DD],
                                             float (*__restrict__ ws)[16][DD],
                                             float* o, int t) {
    o[0] = o[1] = o[2] = o[3] = 0.f;
    int r0 = t >> 6;
    int c0 = (t & 63) * 4;
    float4 pre[4];

#pragma unroll
    for (int j = 0; j < 4; j++)
        pre[j] = *(const float4*)(W + (size_t)(r0 + j * 4) * DD + c0);
#pragma unroll
    for (int j = 0; j < 4; j++)
        *(float4*)&ws[0][r0 + j * 4][c0] = pre[j];
#pragma unroll
    for (int j = 0; j < 4; j++)
        pre[j] = *(const float4*)(W + (size_t)(16 + r0 + j * 4) * DD + c0);
    __syncthreads();

#pragma unroll 1
    for (int ti = 0; ti < 16; ti++) {
        int cur = ti & 1;
        if (ti + 1 < 16) {
#pragma unroll
            for (int j = 0; j < 4; j++)
                *(float4*)&ws[cur ^ 1][r0 + j * 4][c0] = pre[j];
        }
        if (ti + 2 < 16) {
            int d0 = (ti + 2) * 16;
#pragma unroll
            for (int j = 0; j < 4; j++)
                pre[j] = *(const float4*)(W + (size_t)(d0 + r0 + j * 4) * DD + c0);
        }
        int db = ti * 16;
#pragma unroll
        for (int j4 = 0; j4 < 16; j4 += 4) {
            float w0 = ws[cur][j4 + 0][t];
            float w1 = ws[cur][j4 + 1][t];
            float w2 = ws[cur][j4 + 2][t];
            float w3 = ws[cur][j4 + 3][t];
#pragma unroll
            for (int r = 0; r < 4; r++) {
                float4 sv = *(const float4*)&in[r][db + j4];
                o[r] += sv.x * w0 + sv.y * w1 + sv.z * w2 + sv.w * w3;
            }
        }
        __syncthreads();
    }
}

// ---------------- 5) fused MLP + Q + zero ----------------
template<bool DO_MLP, bool DO_Q>
__global__ void __launch_bounds__(256) mlpq_kernel(
    int which,
    const float* __restrict__ lnff_g, const float* __restrict__ lnff_b,
    const float* __restrict__ W1, const float* __restrict__ b1,
    const float* __restrict__ W2, const float* __restrict__ b2,
    const float* __restrict__ lns_g, const float* __restrict__ lns_b,
    const float* __restrict__ Wq, const float* __restrict__ bq)
{
    __shared__ float s1[4][DD];
    __shared__ float sln[4][DD];
    __shared__ float hs[4][DD];
    __shared__ float ws[2][16][DD];
    __shared__ float rs[8], rs2[8];

    float* slots  = which ? g_inst_slots  : g_sem_slots;
    float* q      = which ? g_inst_q      : g_sem_q;
    float* acc    = which ? g_inst_acc    : g_sem_acc;
    float* rowsum = which ? g_inst_rowsum : g_sem_rowsum;

    int t  = threadIdx.x;
    int r0 = blockIdx.x * 4;

    if (DO_MLP) {
        float gg = lnff_g[t], bb = lnff_b[t];
#pragma unroll
        for (int r = 0; r < 4; r++) {
            int row = r0 + r;
            float v = slots[(size_t)row * DD + t] + acc[(size_t)row * DD + t] / rowsum[row];
            s1[r][t] = v;
            float m, inv;
            block_stats(v, rs, rs2, t, m, inv);
            sln[r][t] = (v - m) * inv * gg + bb;
        }
        __syncthreads();
        float h[4];
        gemm4_staged(W1, sln, ws, h, t);
        float b1v = b1[t];
#pragma unroll
        for (int r = 0; r < 4; r++) hs[r][t] = fmaxf(h[r] + b1v, 0.f);
        __syncthreads();
        float o[4];
        gemm4_staged(W2, hs, ws, o, t);
        float b2v = b2[t];
#pragma unroll
        for (int r = 0; r < 4; r++) {
            float nv = s1[r][t] + o[r] + b2v;
            slots[(size_t)(r0 + r) * DD + t] = nv;
            s1[r][t] = nv;
        }
    } else {
#pragma unroll
        for (int r = 0; r < 4; r++) s1[r][t] = slots[(size_t)(r0 + r) * DD + t];
    }

    if (DO_Q) {
        float gg = lns_g[t], bb = lns_b[t];
#pragma unroll
        for (int r = 0; r < 4; r++) {
            int row = r0 + r;
            float v = s1[r][t];
            float m, inv;
            block_stats(v, rs, rs2, t, m, inv);
            sln[r][t] = (v - m) * inv * gg + bb;
            acc[(size_t)row * DD + t] = 0.f;
            if (t == 0) rowsum[row] = 0.f;
        }
        __syncthreads();
        float qa[4];
        gemm4_staged(Wq, sln, ws, qa, t);
        float qb = bq[t];
#pragma unroll
        for (int r = 0; r < 4; r++)
            q[(size_t)(r0 + r) * DD + t] = qa[r] + qb;
    }
}

// ---------------- mma phase helpers (double-buffered staging) ----------------
template<int MT>
__device__ __forceinline__ void dots_phase(const float* __restrict__ kbase,
                                           const float* __restrict__ qs,
                                           float* __restrict__ kt,
                                           float c[MT][4][4], int t) {
    int lane = t & 31, wid = t >> 5;
    int qrow = lane >> 2, qk = lane & 3;
    int wn = wid * 32;
#pragma unroll
    for (int mt = 0; mt < MT; mt++)
#pragma unroll
        for (int nt = 0; nt < 4; nt++)
#pragma unroll
            for (int i = 0; i < 4; i++) c[mt][nt][i] = 0.f;

    const uint32_t* qsu = (const uint32_t*)qs;
    int srow = t >> 3;            // shared across j with +32 stride
    int sc4  = (t & 7) * 4;

    float4 pre[8];
#pragma unroll
    for (int j = 0; j < 8; j++)
        pre[j] = *(const float4*)(kbase + (size_t)(srow + j * 32) * DD + sc4);
    {
#pragma unroll
        for (int j = 0; j < 8; j++) {
            uint32_t* dst = (uint32_t*)&kt[(srow + j * 32) * KTP + sc4];
            dst[0] = f2tf(pre[j].x); dst[1] = f2tf(pre[j].y);
            dst[2] = f2tf(pre[j].z); dst[3] = f2tf(pre[j].w);
        }
#pragma unroll
        for (int j = 0; j < 8; j++)
            pre[j] = *(const float4*)(kbase + (size_t)(srow + j * 32) * DD + 32 + sc4);
    }
    __syncthreads();

#pragma unroll 1
    for (int cc = 0; cc < 8; cc++) {
        const uint32_t* ktu = (const uint32_t*)(kt + (cc & 1) * RBUF);
        if (cc + 1 < 8) {
            float* nxt = kt + ((cc + 1) & 1) * RBUF;
#pragma unroll
            for (int j = 0; j < 8; j++) {
                uint32_t* dst = (uint32_t*)&nxt[(srow + j * 32) * KTP + sc4];
                dst[0] = f2tf(pre[j].x); dst[1] = f2tf(pre[j].y);
                dst[2] = f2tf(pre[j].z); dst[3] = f2tf(pre[j].w);
            }
        }
        if (cc + 2 < 8) {
            int dc = (cc + 2) * 32;
#pragma unroll
            for (int j = 0; j < 8; j++)
                pre[j] = *(const float4*)(kbase + (size_t)(srow + j * 32) * DD + dc + sc4);
        }
        int dc = cc * 32;
#pragma unroll
        for (int k8 = 0; k8 < 4; k8++) {
            uint32_t a[MT][4], b[4][2];
            int kg = dc + k8 * 8 + qk;
            int kl = k8 * 8 + qk;
#pragma unroll
            for (int mt = 0; mt < MT; mt++) {
                int m0 = mt * 16 + qrow;
                a[mt][0] = qsu[m0 * PQ + kg];
                a[mt][1] = qsu[(m0 + 8) * PQ + kg];
                a[mt][2] = qsu[m0 * PQ + kg + 4];
                a[mt][3] = qsu[(m0 + 8) * PQ + kg + 4];
            }
#pragma unroll
            for (int nt = 0; nt < 4; nt++) {
                int n = wn + nt * 8 + qrow;
                b[nt][0] = ktu[n * KTP + kl];
                b[nt][1] = ktu[n * KTP + kl + 4];
            }
#pragma unroll
            for (int mt = 0; mt < MT; mt++)
#pragma unroll
                for (int nt = 0; nt < 4; nt++)
                    mma_tf32(c[mt][nt], a[mt], b[nt]);
        }
        __syncthreads();
    }
}

template<int MT, int PD>
__device__ __forceinline__ void store_dots(float c[MT][4][4], float* __restrict__ dotm, int t) {
    int lane = t & 31, wid = t >> 5;
    int qrow = lane >> 2, qk = lane & 3;
    int wn = wid * 32;
#pragma unroll
    for (int mt = 0; mt < MT; mt++)
#pragma unroll
        for (int nt = 0; nt < 4; nt++) {
            int tok = wn + nt * 8 + 2 * qk;
            int m0  = mt * 16 + qrow;
            dotm[tok * PD + m0]           = c[mt][nt][0] * SCALE_F;
            dotm[(tok + 1) * PD + m0]     = c[mt][nt][1] * SCALE_F;
            dotm[tok * PD + m0 + 8]       = c[mt][nt][2] * SCALE_F;
            dotm[(tok + 1) * PD + m0 + 8] = c[mt][nt][3] * SCALE_F;
        }
}

template<int MT>
__device__ __forceinline__ void upd_phase(const float* __restrict__ vbase,
                                          const float* __restrict__ atm,
                                          float* __restrict__ vt,
                                          float c[MT][4][4], int t) {
    int lane = t & 31, wid = t >> 5;
    int qrow = lane >> 2, qk = lane & 3;
    int wd = wid * 32;
#pragma unroll
    for (int mt = 0; mt < MT; mt++)
#pragma unroll
        for (int nt = 0; nt < 4; nt++)
#pragma unroll
            for (int i = 0; i < 4; i++) c[mt][nt][i] = 0.f;

    const uint32_t* au = (const uint32_t*)atm;
    int srow = t >> 6;            // 0..3, rows stride 4 across j
    int sc4  = (t & 63) * 4;

    float4 pre[8];
#pragma unroll
    for (int j = 0; j < 8; j++)
        pre[j] = *(const float4*)(vbase + (size_t)(srow + j * 4) * DD + sc4);
    {
#pragma unroll
        for (int j = 0; j < 8; j++) {
            uint32_t* dst = (uint32_t*)&vt[(srow + j * 4) * PV + sc4];
            dst[0] = f2tf(pre[j].x); dst[1] = f2tf(pre[j].y);
            dst[2] = f2tf(pre[j].z); dst[3] = f2tf(pre[j].w);
        }
#pragma unroll
        for (int j = 0; j < 8; j++)
            pre[j] = *(const float4*)(vbase + (size_t)(32 + srow + j * 4) * DD + sc4);
    }
    __syncthreads();

#pragma unroll 1
    for (int cc = 0; cc < 8; cc++) {
        const uint32_t* vu = (const uint32_t*)(vt + (cc & 1) * RBUF);
        if (cc + 1 < 8) {
            float* nxt = vt + ((cc + 1) & 1) * RBUF;
#pragma unroll
            for (int j = 0; j < 8; j++) {
                uint32_t* dst = (uint32_t*)&nxt[(srow + j * 4) * PV + sc4];
                dst[0] = f2tf(pre[j].x); dst[1] = f2tf(pre[j].y);
                dst[2] = f2tf(pre[j].z); dst[3] = f2tf(pre[j].w);
            }
        }
        if (cc + 2 < 8) {
            int tc = (cc + 2) * 32;
#pragma unroll
            for (int j = 0; j < 8; j++)
                pre[j] = *(const float4*)(vbase + (size_t)(tc + srow + j * 4) * DD + sc4);
        }
        int tc = cc * 32;
#pragma unroll
        for (int k8 = 0; k8 < 4; k8++) {
            uint32_t a[MT][4], b[4][2];
            int kg = tc + k8 * 8 + qk;
            int kl = k8 * 8 + qk;
#pragma unroll
            for (int mt = 0; mt < MT; mt++) {
                int m0 = mt * 16 + qrow;
                a[mt][0] = au[m0 * PQ + kg];
                a[mt][1] = au[(m0 + 8) * PQ + kg];
                a[mt][2] = au[m0 * PQ + kg + 4];
                a[mt][3] = au[(m0 + 8) * PQ + kg + 4];
            }
#pragma unroll
            for (int nt = 0; nt < 4; nt++) {
                int d = wd + nt * 8 + qrow;
                b[nt][0] = vu[kl * PV + d];
                b[nt][1] = vu[(kl + 4) * PV + d];
            }
#pragma unroll
            for (int mt = 0; mt < MT; mt++)
#pragma unroll
                for (int nt = 0; nt < 4; nt++)
                    mma_tf32(c[mt][nt], a[mt], b[nt]);
        }
        __syncthreads();
    }
}

template<int MT, int NRS>
__device__ __forceinline__ void upd_atomics(float c[MT][4][4], float* __restrict__ gacc,
                                            int slot_base, int t) {
    int lane = t & 31, wid = t >> 5;
    int qrow = lane >> 2, qk = lane & 3;
    int wd = wid * 32;
#pragma unroll
    for (int mt = 0; mt < MT; mt++)
#pragma unroll
        for (int nt = 0; nt < 4; nt++) {
            int d  = wd + nt * 8 + 2 * qk;
            int s0 = mt * 16 + qrow;
            atomicAdd(&gacc[(size_t)(slot_base + s0) * DD + d],     c[mt][nt][0]);
            atomicAdd(&gacc[(size_t)(slot_base + s0) * DD + d + 1], c[mt][nt][1]);
            if (s0 + 8 < NRS) {
                atomicAdd(&gacc[(size_t)(slot_base + s0 + 8) * DD + d],     c[mt][nt][2]);
                atomicAdd(&gacc[(size_t)(slot_base + s0 + 8) * DD + d + 1], c[mt][nt][3]);
            }
        }
}

// ---------------- 6) fused sem (mma) ----------------
__global__ void __launch_bounds__(256) sem_fused_kernel(int write_dots) {
    extern __shared__ float smem[];
    float* qs   = smem;                 // 16*PQ
    float* reg2 = smem + 16 * PQ;       // 2*RBUF
    const int PD = 17;

    int b  = blockIdx.y;
    int n0 = blockIdx.x * 256;
    int t  = threadIdx.x;
    int n  = n0 + t;

    for (int idx = t; idx < NSL * DD; idx += 256) {
        int r = idx >> 8, cc = idx & 255;
        ((uint32_t*)qs)[r * PQ + cc] = f2tf(g_sem_q[(size_t)b * NSL * DD + idx]);
    }
    for (int idx = t; idx < 8 * DD; idx += 256) {
        int r = idx >> 8, cc = idx & 255;
        qs[(NSL + r) * PQ + cc] = 0.f;
    }
    // no sync needed before dots_phase's internal first sync

    float c[1][4][4];
    dots_phase<1>(g_k + ((size_t)b * NN + n0) * DD, qs, reg2, c, t);

    store_dots<1, PD>(c, reg2, t);      // last phase sync protects buffers
    __syncthreads();

    float dv[NSL], e[NSL];
    float mx = -1e30f;
#pragma unroll
    for (int i = 0; i < NSL; i++) { dv[i] = reg2[t * PD + i]; mx = fmaxf(mx, dv[i]); }
    float ssum = 0.f;
#pragma unroll
    for (int i = 0; i < NSL; i++) { e[i] = expf(dv[i] - mx); ssum += e[i]; }
    float inv = 1.0f / ssum;

    size_t base = (size_t)b * NSL * NN + n;
    int l = t & 31;
    float at[NSL];
#pragma unroll
    for (int i = 0; i < NSL; i++) {
        at[i] = e[i] * inv + EPS_F;
        if (write_dots) g_sem_dots[base + (size_t)i * NN] = dv[i];
        float sv = warp_sum(at[i]);
        if (l == 0) atomicAdd(&g_sem_rowsum[b * NSL + i], sv);
    }

    __syncthreads();
#pragma unroll
    for (int i = 0; i < NSL; i++)
        ((uint32_t*)qs)[i * PQ + t] = f2tf(at[i]);
#pragma unroll
    for (int i = NSL; i < 16; i++)
        qs[i * PQ + t] = 0.f;
    __syncthreads();

    float c2[1][4][4];
    upd_phase<1>(g_v + ((size_t)b * NN + n0) * DD, qs, reg2, c2, t);
    upd_atomics<1, NSL>(c2, g_sem_acc, b * NSL, t);
}

// ---------------- 7) fused inst (mma) ----------------
__global__ void __launch_bounds__(256) inst_fused_kernel(int write_dots) {
    extern __shared__ float smem[];
    float* qs   = smem;                 // 32*PQ
    float* reg2 = smem + 32 * PQ;       // 2*RBUF
    const int PD = 33;

    int b  = blockIdx.y;
    int n0 = blockIdx.x * 256;
    int t  = threadIdx.x;
    int n  = n0 + t;

    for (int idx = t; idx < 32 * DD; idx += 256) {
        int r = idx >> 8, cc = idx & 255;
        ((uint32_t*)qs)[r * PQ + cc] = f2tf(g_inst_q[(size_t)b * 32 * DD + idx]);
    }

    float c[2][4][4];
    dots_phase<2>(g_k + ((size_t)b * NN + n0) * DD, qs, reg2, c, t);

    store_dots<2, PD>(c, reg2, t);
    __syncthreads();

    float wv[NSL];
    {
        size_t sbase = (size_t)b * NSL * NN + n;
        float sdv[NSL];
        float smx = -1e30f;
#pragma unroll
        for (int i = 0; i < NSL; i++) { sdv[i] = g_sem_dots[sbase + (size_t)i * NN]; smx = fmaxf(smx, sdv[i]); }
        float ss = 0.f;
#pragma unroll
        for (int i = 0; i < NSL; i++) { sdv[i] = expf(sdv[i] - smx); ss += sdv[i]; }
        float sinv = 1.0f / ss;
#pragma unroll
        for (int i = 0; i < NSL; i++) wv[i] = sdv[i] * sinv;
    }

    size_t dbase = (size_t)b * 32 * NN + n;
    int l = t & 31;
    float at[32];
#pragma unroll
    for (int s = 0; s < 8; s++) {
        float dv[NPI], e[NPI];
        float mx = -1e30f;
#pragma unroll
        for (int p = 0; p < NPI; p++) { dv[p] = reg2[t * PD + s * 4 + p]; mx = fmaxf(mx, dv[p]); }
        float ssum = 0.f;
#pragma unroll
        for (int p = 0; p < NPI; p++) { e[p] = expf(dv[p] - mx); ssum += e[p]; }
        float invs = 1.0f / ssum;
#pragma unroll
        for (int p = 0; p < NPI; p++) {
            int sp = s * 4 + p;
            at[sp] = (e[p] * invs + EPS_F) * wv[s];
            if (write_dots) g_inst_dots[dbase + (size_t)sp * NN] = dv[p];
            float sv = warp_sum(at[sp]);
            if (l == 0) atomicAdd(&g_inst_rowsum[b * 32 + sp], sv);
        }
    }

    __syncthreads();
#pragma unroll
    for (int i = 0; i < 32; i++)
        ((uint32_t*)qs)[i * PQ + t] = f2tf(at[i]);
    __syncthreads();

    float c2[2][4][4];
    upd_phase<2>(g_v + ((size_t)b * NN + n0) * DD, qs, reg2, c2, t);
    upd_atomics<2, 32>(c2, g_inst_acc, b * 32, t);
}

// ---------------- 8) assemble output ----------------
__global__ void __launch_bounds__(256) write_out_kernel(float* __restrict__ out) {
    size_t idx = (size_t)blockIdx.x * 256 + threadIdx.x;
    const size_t A1 = 32768;
    const size_t A2 = 557056;
    const size_t A3 = 688128;
    const size_t A4 = 2785280;
    if (idx >= A4) return;
    float v;
    if (idx < A1)      v = g_sem_slots[idx];
    else if (idx < A2) v = g_sem_dots[idx - A1];
    else if (idx < A3) v = g_inst_slots[idx - A2];
    else               v = g_inst_dots[idx - A3];
    out[idx] = v;
}

// ---------------- launch ----------------
extern "C" void kernel_launch(void* const* d_in, const int* in_sizes, int n_in,
                              void* d_out, int out_size) {
    (void)in_sizes; (void)n_in; (void)out_size;
    const float* inputs      = (const float*)d_in[0];
    const float* noise       = (const float*)d_in[3];
    const float* ln_in_g     = (const float*)d_in[4];
    const float* ln_in_b     = (const float*)d_in[5];
    const float* ln_s_g      = (const float*)d_in[6];
    const float* ln_s_b      = (const float*)d_in[7];
    const float* ln_ff_g     = (const float*)d_in[8];
    const float* ln_ff_b     = (const float*)d_in[9];
    const float* slots_mu    = (const float*)d_in[10];
    const float* slots_sigma = (const float*)d_in[11];
    const float* Wq          = (const float*)d_in[12];
    const float* bq          = (const float*)d_in[13];
    const float* Wk          = (const float*)d_in[14];
    const float* bk          = (const float*)d_in[15];
    const float* Wv          = (const float*)d_in[16];
    const float* bv          = (const float*)d_in[17];
    const float* W1          = (const float*)d_in[18];
    const float* b1          = (const float*)d_in[19];
    const float* W2          = (const float*)d_in[20];
    const float* b2          = (const float*)d_in[21];
    float* out = (float*)d_out;

    const int sem_smem  = (16 * PQ + 2 * RBUF) * 4;   // 90,368 B
    const int inst_smem = (32 * PQ + 2 * RBUF) * 4;   // 107,008 B
    static int attr_done = 0;
    if (!attr_done) {
        cudaFuncSetAttribute(sem_fused_kernel,  cudaFuncAttributeMaxDynamicSharedMemorySize, sem_smem);
        cudaFuncSetAttribute(inst_fused_kernel, cudaFuncAttributeMaxDynamicSharedMemorySize, inst_smem);
        attr_done = 1;
    }

    ln_input_kernel<<<BB * NN, 256>>>(inputs, ln_in_g, ln_in_b);

    dim3 gemm_grid(4, 512);
    gemm_tf32_kernel<<<gemm_grid, 256>>>(Wk, bk, Wv, bv);

    sem_init_kernel<<<BB * NSL, 256>>>(slots_mu);

    dim3 bn_grid(16, 16);
    const int SEM_BLKS  = BB * NSL / 4;        // 32
    const int INST_BLKS = BB * NSL * NPI / 4;  // 128

    mlpq_kernel<false, true><<<SEM_BLKS, 256>>>(0, ln_ff_g, ln_ff_b, W1, b1, W2, b2,
                                                ln_s_g, ln_s_b, Wq, bq);
    for (int it = 0; it < 3; it++) {
        sem_fused_kernel<<<bn_grid, 256, sem_smem>>>(it == 2 ? 1 : 0);
        if (it < 2)
            mlpq_kernel<true, true><<<SEM_BLKS, 256>>>(0, ln_ff_g, ln_ff_b, W1, b1, W2, b2,
                                                       ln_s_g, ln_s_b, Wq, bq);
        else
            mlpq_kernel<true, false><<<SEM_BLKS, 256>>>(0, ln_ff_g, ln_ff_b, W1, b1, W2, b2,
                                                        ln_s_g, ln_s_b, Wq, bq);
    }

    inst_init_kernel<<<BB * NSL * NPI, 256>>>(slots_mu, slots_sigma, noise);

    mlpq_kernel<false, true><<<INST_BLKS, 256>>>(1, ln_ff_g, ln_ff_b, W1, b1, W2, b2,
                                                 ln_s_g, ln_s_b, Wq, bq);
    for (int it = 0; it < 3; it++) {
        inst_fused_kernel<<<bn_grid, 256, inst_smem>>>(it == 2 ? 1 : 0);
        if (it < 2)
            mlpq_kernel<true, true><<<INST_BLKS, 256>>>(1, ln_ff_g, ln_ff_b, W1, b1, W2, b2,
                                                        ln_s_g, ln_s_b, Wq, bq);
        else
            mlpq_kernel<true, false><<<INST_BLKS, 256>>>(1, ln_ff_g, ln_ff_b, W1, b1, W2, b2,
                                                         ln_s_g, ln_s_b, Wq, bq);
    }

    write_out_kernel<<<10880, 256>>>(out);
}

// round 9
// speedup vs baseline: 2.5401x; 1.0461x over previous
#include <cuda_runtime.h>
#include <math.h>
#include <stdint.h>

#define BB   16
#define NN   4096
#define DD   256
#define NSL  8
#define NPI  4
#define HH   256
#define SCALE_F 0.0625f
#define EPS_F   1e-8f

#define KTP 36    // k-tile pitch (fused kernels)
#define PQ  260   // q/attn pitch
#define PV  264   // v-tile pitch
#define RBUF 9216 // floats per staging buffer (fused kernels)

#define AP   36      // gemm smem pitch ([m][k] / [n][k])
#define GBUF 9216    // u32 per gemm double buffer (As 4608 + Bs 4608)

// ---------------- scratch ----------------
__device__ uint32_t g_xi[BB*NN*DD];      // LN(x) as tf32 bits, row-major [M][K]
__device__ uint32_t g_wt[2*DD*DD];       // W transposed tf32: [mat][n][k]
__device__ float g_k[BB*NN*DD];
__device__ float g_v[BB*NN*DD];

__device__ float g_sem_slots[BB*NSL*DD];
__device__ float g_sem_q[BB*NSL*DD];
__device__ float g_sem_dots[BB*NSL*NN];
__device__ float g_sem_rowsum[BB*NSL];
__device__ float g_sem_acc[BB*NSL*DD];

__device__ float g_inst_slots[BB*NSL*NPI*DD];
__device__ float g_inst_q[BB*NSL*NPI*DD];
__device__ float g_inst_dots[BB*NSL*NPI*NN];
__device__ float g_inst_rowsum[BB*NSL*NPI];
__device__ float g_inst_acc[BB*NSL*NPI*DD];

// ---------------- helpers ----------------
__device__ __forceinline__ float warp_sum(float v) {
#pragma unroll
    for (int o = 16; o; o >>= 1) v += __shfl_xor_sync(0xffffffffu, v, o);
    return v;
}

__device__ __forceinline__ void block_stats(float v, float* rs, float* rs2, int t,
                                            float& m, float& inv) {
    float s  = warp_sum(v);
    float s2 = warp_sum(v * v);
    if ((t & 31) == 0) { rs[t >> 5] = s; rs2[t >> 5] = s2; }
    __syncthreads();
    float sum = 0.f, sum2 = 0.f;
#pragma unroll
    for (int i = 0; i < 8; i++) { sum += rs[i]; sum2 += rs2[i]; }
    m = sum * (1.0f / 256.0f);
    float var = sum2 * (1.0f / 256.0f) - m * m;
    inv = rsqrtf(var + 1e-5f);
    __syncthreads();
}

__device__ __forceinline__ uint32_t f2tf(float f) {
    uint32_t u;
    asm("cvt.rna.tf32.f32 %0, %1;" : "=r"(u) : "f"(f));
    return u;
}

__device__ __forceinline__ void mma_tf32(float* c, const uint32_t* a, const uint32_t* b) {
    asm volatile("mma.sync.aligned.m16n8k8.row.col.f32.tf32.tf32.f32 "
        "{%0,%1,%2,%3}, {%4,%5,%6,%7}, {%8,%9}, {%0,%1,%2,%3};"
        : "+f"(c[0]), "+f"(c[1]), "+f"(c[2]), "+f"(c[3])
        : "r"(a[0]), "r"(a[1]), "r"(a[2]), "r"(a[3]), "r"(b[0]), "r"(b[1]));
}

// ---------------- 1) LN over inputs -> tf32 bits ----------------
__global__ void __launch_bounds__(256) ln_input_kernel(const float* __restrict__ x,
                                                       const float* __restrict__ g,
                                                       const float* __restrict__ b) {
    __shared__ float rs[8], rs2[8];
    int row = blockIdx.x;
    int t   = threadIdx.x;
    float v = x[(size_t)row * DD + t];
    float m, inv;
    block_stats(v, rs, rs2, t, m, inv);
    g_xi[(size_t)row * DD + t] = f2tf((v - m) * inv * g[t] + b[t]);
}

// ---------------- 1b) transpose W -> g_wt[mat][n][k] tf32 ----------------
__global__ void __launch_bounds__(256) prep_b_kernel(const float* __restrict__ Wk,
                                                     const float* __restrict__ Wv) {
    __shared__ float tile[32][33];
    int bi = blockIdx.x;             // 0..127
    int mat = bi >> 6;
    int tid = bi & 63;
    int tn0 = (tid & 7) * 32;
    int tk0 = (tid >> 3) * 32;
    const float* W = mat ? Wv : Wk;
    int t = threadIdx.x;
    int c = t & 31, r = t >> 5;      // 32 x 8
#pragma unroll
    for (int j = 0; j < 4; j++) {
        int kl = r + j * 8;
        tile[c][kl] = W[(size_t)(tk0 + kl) * DD + tn0 + c];
    }
    __syncthreads();
#pragma unroll
    for (int j = 0; j < 4; j++) {
        int nl = r + j * 8;
        g_wt[(size_t)mat * DD * DD + (size_t)(tn0 + nl) * DD + tk0 + c] = f2tf(tile[nl][c]);
    }
}

// ---------------- 2) TF32 GEMM (double-buffered, pre-converted operands) ----------------
// grid (4, 512): x = mat*2 + nhalf, y = m-tile. C[128,128] per CTA.
__global__ void __launch_bounds__(256) gemm_tf32_kernel(const float* __restrict__ bk,
                                                        const float* __restrict__ bv) {
    extern __shared__ uint32_t smu[];   // [2][GBUF]: As[128][36] + Bs[128][36]

    int t = threadIdx.x;
    int mat = blockIdx.x >> 1;
    const float* bias = mat ? bv : bk;
    float* C          = mat ? g_v : g_k;
    int nbase = (blockIdx.x & 1) * 128;
    size_t mbase = (size_t)blockIdx.y * 128;

    int wid = t >> 5, lane = t & 31;
    int wm = (wid >> 1) * 32;
    int wn = (wid & 1) * 64;
    int qrow = lane >> 2;
    int qk   = lane & 3;

    float c[2][8][4];
#pragma unroll
    for (int mt = 0; mt < 2; mt++)
#pragma unroll
        for (int nt = 0; nt < 8; nt++)
#pragma unroll
            for (int i = 0; i < 4; i++) c[mt][nt][i] = 0.f;

    // staging geometry: 1024 uint4 per operand per chunk; 4 per thread
    int srow = t >> 1;               // shared row 0..127 (two threads per row)
    int sc4  = (t & 1) * 16;         // u32 col 0 or 16; +4 per j
    const uint4* asrc = (const uint4*)(g_xi + (mbase + srow) * 256 + sc4);
    const uint4* bsrc = (const uint4*)(g_wt + (size_t)mat * DD * DD + (size_t)(nbase + srow) * 256 + sc4);

    uint4 preA[4], preB[4];
#pragma unroll
    for (int j = 0; j < 4; j++) { preA[j] = asrc[j]; preB[j] = bsrc[j]; }
    {
        uint32_t* As = smu;
        uint32_t* Bs = smu + 4608;
#pragma unroll
        for (int j = 0; j < 4; j++) {
            *(uint4*)&As[srow * AP + sc4 + j * 4] = preA[j];
            *(uint4*)&Bs[srow * AP + sc4 + j * 4] = preB[j];
        }
#pragma unroll
        for (int j = 0; j < 4; j++) { preA[j] = asrc[8 + j]; preB[j] = bsrc[8 + j]; }
    }
    __syncthreads();

#pragma unroll 1
    for (int cc = 0; cc < 8; cc++) {
        const uint32_t* As = smu + (cc & 1) * GBUF;
        const uint32_t* Bs = As + 4608;
        if (cc + 1 < 8) {
            uint32_t* An = smu + ((cc + 1) & 1) * GBUF;
            uint32_t* Bn = An + 4608;
#pragma unroll
            for (int j = 0; j < 4; j++) {
                *(uint4*)&An[srow * AP + sc4 + j * 4] = preA[j];
                *(uint4*)&Bn[srow * AP + sc4 + j * 4] = preB[j];
            }
        }
        if (cc + 2 < 8) {
            int off = (cc + 2) * 8;  // uint4 offset within row (32 u32 per chunk = 8 uint4)
#pragma unroll
            for (int j = 0; j < 4; j++) { preA[j] = asrc[off + j]; preB[j] = bsrc[off + j]; }
        }
#pragma unroll
        for (int k8 = 0; k8 < 4; k8++) {
            int kb = k8 * 8 + qk;
            uint32_t a[2][4], b[8][2];
#pragma unroll
            for (int mt = 0; mt < 2; mt++) {
                int m = wm + mt * 16 + qrow;
                a[mt][0] = As[m * AP + kb];
                a[mt][1] = As[(m + 8) * AP + kb];
                a[mt][2] = As[m * AP + kb + 4];
                a[mt][3] = As[(m + 8) * AP + kb + 4];
            }
#pragma unroll
            for (int nt = 0; nt < 8; nt++) {
                int n = wn + nt * 8 + qrow;
                b[nt][0] = Bs[n * AP + kb];
                b[nt][1] = Bs[n * AP + kb + 4];
            }
#pragma unroll
            for (int mt = 0; mt < 2; mt++)
#pragma unroll
                for (int nt = 0; nt < 8; nt++)
                    mma_tf32(c[mt][nt], a[mt], b[nt]);
        }
        __syncthreads();
    }

#pragma unroll
    for (int mt = 0; mt < 2; mt++) {
        int r0 = wm + mt * 16 + qrow;
#pragma unroll
        for (int nt = 0; nt < 8; nt++) {
            int col = nbase + wn + nt * 8 + 2 * qk;
            float b0v = bias[col], b1v = bias[col + 1];
            size_t base0 = (mbase + r0) * 256 + col;
            size_t base1 = (mbase + r0 + 8) * 256 + col;
            *(float2*)(C + base0) = make_float2(c[mt][nt][0] + b0v, c[mt][nt][1] + b1v);
            *(float2*)(C + base1) = make_float2(c[mt][nt][2] + b0v, c[mt][nt][3] + b1v);
        }
    }
}

// ---------------- 3) init kernels ----------------
__global__ void sem_init_kernel(const float* __restrict__ mu) {
    int r = blockIdx.x;
    int i = r & 7;
    g_sem_slots[(size_t)r * DD + threadIdx.x] = mu[i * DD + threadIdx.x];
}

__global__ void inst_init_kernel(const float* __restrict__ mu,
                                 const float* __restrict__ sigma,
                                 const float* __restrict__ noise) {
    size_t idx = (size_t)blockIdx.x * 256 + threadIdx.x;
    int d = idx & 255;
    int s = (idx >> 10) & 7;
    g_inst_slots[idx] = mu[s * DD + d] + expf(sigma[s * DD + d]) * noise[idx];
}

// ---------------- 4) double-buffered staged GEMV (4 rows/block) ----------------
__device__ __forceinline__ void gemm4_staged(const float* __restrict__ W,
                                             const float (*__restrict__ in)[DD],
                                             float (*__restrict__ ws)[16][DD],
                                             float* o, int t) {
    o[0] = o[1] = o[2] = o[3] = 0.f;
    int r0 = t >> 6;
    int c0 = (t & 63) * 4;
    float4 pre[4];

#pragma unroll
    for (int j = 0; j < 4; j++)
        pre[j] = *(const float4*)(W + (size_t)(r0 + j * 4) * DD + c0);
#pragma unroll
    for (int j = 0; j < 4; j++)
        *(float4*)&ws[0][r0 + j * 4][c0] = pre[j];
#pragma unroll
    for (int j = 0; j < 4; j++)
        pre[j] = *(const float4*)(W + (size_t)(16 + r0 + j * 4) * DD + c0);
    __syncthreads();

#pragma unroll 1
    for (int ti = 0; ti < 16; ti++) {
        int cur = ti & 1;
        if (ti + 1 < 16) {
#pragma unroll
            for (int j = 0; j < 4; j++)
                *(float4*)&ws[cur ^ 1][r0 + j * 4][c0] = pre[j];
        }
        if (ti + 2 < 16) {
            int d0 = (ti + 2) * 16;
#pragma unroll
            for (int j = 0; j < 4; j++)
                pre[j] = *(const float4*)(W + (size_t)(d0 + r0 + j * 4) * DD + c0);
        }
        int db = ti * 16;
#pragma unroll
        for (int j4 = 0; j4 < 16; j4 += 4) {
            float w0 = ws[cur][j4 + 0][t];
            float w1 = ws[cur][j4 + 1][t];
            float w2 = ws[cur][j4 + 2][t];
            float w3 = ws[cur][j4 + 3][t];
#pragma unroll
            for (int r = 0; r < 4; r++) {
                float4 sv = *(const float4*)&in[r][db + j4];
                o[r] += sv.x * w0 + sv.y * w1 + sv.z * w2 + sv.w * w3;
            }
        }
        __syncthreads();
    }
}

// ---------------- 5) fused MLP + Q + zero ----------------
template<bool DO_MLP, bool DO_Q>
__global__ void __launch_bounds__(256) mlpq_kernel(
    int which,
    const float* __restrict__ lnff_g, const float* __restrict__ lnff_b,
    const float* __restrict__ W1, const float* __restrict__ b1,
    const float* __restrict__ W2, const float* __restrict__ b2,
    const float* __restrict__ lns_g, const float* __restrict__ lns_b,
    const float* __restrict__ Wq, const float* __restrict__ bq)
{
    __shared__ float s1[4][DD];
    __shared__ float sln[4][DD];
    __shared__ float hs[4][DD];
    __shared__ float ws[2][16][DD];
    __shared__ float rs[8], rs2[8];

    float* slots  = which ? g_inst_slots  : g_sem_slots;
    float* q      = which ? g_inst_q      : g_sem_q;
    float* acc    = which ? g_inst_acc    : g_sem_acc;
    float* rowsum = which ? g_inst_rowsum : g_sem_rowsum;

    int t  = threadIdx.x;
    int r0 = blockIdx.x * 4;

    if (DO_MLP) {
        float gg = lnff_g[t], bb = lnff_b[t];
#pragma unroll
        for (int r = 0; r < 4; r++) {
            int row = r0 + r;
            float v = slots[(size_t)row * DD + t] + acc[(size_t)row * DD + t] / rowsum[row];
            s1[r][t] = v;
            float m, inv;
            block_stats(v, rs, rs2, t, m, inv);
            sln[r][t] = (v - m) * inv * gg + bb;
        }
        __syncthreads();
        float h[4];
        gemm4_staged(W1, sln, ws, h, t);
        float b1v = b1[t];
#pragma unroll
        for (int r = 0; r < 4; r++) hs[r][t] = fmaxf(h[r] + b1v, 0.f);
        __syncthreads();
        float o[4];
        gemm4_staged(W2, hs, ws, o, t);
        float b2v = b2[t];
#pragma unroll
        for (int r = 0; r < 4; r++) {
            float nv = s1[r][t] + o[r] + b2v;
            slots[(size_t)(r0 + r) * DD + t] = nv;
            s1[r][t] = nv;
        }
    } else {
#pragma unroll
        for (int r = 0; r < 4; r++) s1[r][t] = slots[(size_t)(r0 + r) * DD + t];
    }

    if (DO_Q) {
        float gg = lns_g[t], bb = lns_b[t];
#pragma unroll
        for (int r = 0; r < 4; r++) {
            int row = r0 + r;
            float v = s1[r][t];
            float m, inv;
            block_stats(v, rs, rs2, t, m, inv);
            sln[r][t] = (v - m) * inv * gg + bb;
            acc[(size_t)row * DD + t] = 0.f;
            if (t == 0) rowsum[row] = 0.f;
        }
        __syncthreads();
        float qa[4];
        gemm4_staged(Wq, sln, ws, qa, t);
        float qb = bq[t];
#pragma unroll
        for (int r = 0; r < 4; r++)
            q[(size_t)(r0 + r) * DD + t] = qa[r] + qb;
    }
}

// ---------------- mma phase helpers (double-buffered staging) ----------------
template<int MT>
__device__ __forceinline__ void dots_phase(const float* __restrict__ kbase,
                                           const float* __restrict__ qs,
                                           float* __restrict__ kt,
                                           float c[MT][4][4], int t) {
    int lane = t & 31, wid = t >> 5;
    int qrow = lane >> 2, qk = lane & 3;
    int wn = wid * 32;
#pragma unroll
    for (int mt = 0; mt < MT; mt++)
#pragma unroll
        for (int nt = 0; nt < 4; nt++)
#pragma unroll
            for (int i = 0; i < 4; i++) c[mt][nt][i] = 0.f;

    const uint32_t* qsu = (const uint32_t*)qs;
    int srow = t >> 3;
    int sc4  = (t & 7) * 4;

    float4 pre[8];
#pragma unroll
    for (int j = 0; j < 8; j++)
        pre[j] = *(const float4*)(kbase + (size_t)(srow + j * 32) * DD + sc4);
    {
#pragma unroll
        for (int j = 0; j < 8; j++) {
            uint32_t* dst = (uint32_t*)&kt[(srow + j * 32) * KTP + sc4];
            dst[0] = f2tf(pre[j].x); dst[1] = f2tf(pre[j].y);
            dst[2] = f2tf(pre[j].z); dst[3] = f2tf(pre[j].w);
        }
#pragma unroll
        for (int j = 0; j < 8; j++)
            pre[j] = *(const float4*)(kbase + (size_t)(srow + j * 32) * DD + 32 + sc4);
    }
    __syncthreads();

#pragma unroll 1
    for (int cc = 0; cc < 8; cc++) {
        const uint32_t* ktu = (const uint32_t*)(kt + (cc & 1) * RBUF);
        if (cc + 1 < 8) {
            float* nxt = kt + ((cc + 1) & 1) * RBUF;
#pragma unroll
            for (int j = 0; j < 8; j++) {
                uint32_t* dst = (uint32_t*)&nxt[(srow + j * 32) * KTP + sc4];
                dst[0] = f2tf(pre[j].x); dst[1] = f2tf(pre[j].y);
                dst[2] = f2tf(pre[j].z); dst[3] = f2tf(pre[j].w);
            }
        }
        if (cc + 2 < 8) {
            int dc = (cc + 2) * 32;
#pragma unroll
            for (int j = 0; j < 8; j++)
                pre[j] = *(const float4*)(kbase + (size_t)(srow + j * 32) * DD + dc + sc4);
        }
        int dc = cc * 32;
#pragma unroll
        for (int k8 = 0; k8 < 4; k8++) {
            uint32_t a[MT][4], b[4][2];
            int kg = dc + k8 * 8 + qk;
            int kl = k8 * 8 + qk;
#pragma unroll
            for (int mt = 0; mt < MT; mt++) {
                int m0 = mt * 16 + qrow;
                a[mt][0] = qsu[m0 * PQ + kg];
                a[mt][1] = qsu[(m0 + 8) * PQ + kg];
                a[mt][2] = qsu[m0 * PQ + kg + 4];
                a[mt][3] = qsu[(m0 + 8) * PQ + kg + 4];
            }
#pragma unroll
            for (int nt = 0; nt < 4; nt++) {
                int n = wn + nt * 8 + qrow;
                b[nt][0] = ktu[n * KTP + kl];
                b[nt][1] = ktu[n * KTP + kl + 4];
            }
#pragma unroll
            for (int mt = 0; mt < MT; mt++)
#pragma unroll
                for (int nt = 0; nt < 4; nt++)
                    mma_tf32(c[mt][nt], a[mt], b[nt]);
        }
        __syncthreads();
    }
}

template<int MT, int PD>
__device__ __forceinline__ void store_dots(float c[MT][4][4], float* __restrict__ dotm, int t) {
    int lane = t & 31, wid = t >> 5;
    int qrow = lane >> 2, qk = lane & 3;
    int wn = wid * 32;
#pragma unroll
    for (int mt = 0; mt < MT; mt++)
#pragma unroll
        for (int nt = 0; nt < 4; nt++) {
            int tok = wn + nt * 8 + 2 * qk;
            int m0  = mt * 16 + qrow;
            dotm[tok * PD + m0]           = c[mt][nt][0] * SCALE_F;
            dotm[(tok + 1) * PD + m0]     = c[mt][nt][1] * SCALE_F;
            dotm[tok * PD + m0 + 8]       = c[mt][nt][2] * SCALE_F;
            dotm[(tok + 1) * PD + m0 + 8] = c[mt][nt][3] * SCALE_F;
        }
}

template<int MT>
__device__ __forceinline__ void upd_phase(const float* __restrict__ vbase,
                                          const float* __restrict__ atm,
                                          float* __restrict__ vt,
                                          float c[MT][4][4], int t) {
    int lane = t & 31, wid = t >> 5;
    int qrow = lane >> 2, qk = lane & 3;
    int wd = wid * 32;
#pragma unroll
    for (int mt = 0; mt < MT; mt++)
#pragma unroll
        for (int nt = 0; nt < 4; nt++)
#pragma unroll
            for (int i = 0; i < 4; i++) c[mt][nt][i] = 0.f;

    const uint32_t* au = (const uint32_t*)atm;
    int srow = t >> 6;
    int sc4  = (t & 63) * 4;

    float4 pre[8];
#pragma unroll
    for (int j = 0; j < 8; j++)
        pre[j] = *(const float4*)(vbase + (size_t)(srow + j * 4) * DD + sc4);
    {
#pragma unroll
        for (int j = 0; j < 8; j++) {
            uint32_t* dst = (uint32_t*)&vt[(srow + j * 4) * PV + sc4];
            dst[0] = f2tf(pre[j].x); dst[1] = f2tf(pre[j].y);
            dst[2] = f2tf(pre[j].z); dst[3] = f2tf(pre[j].w);
        }
#pragma unroll
        for (int j = 0; j < 8; j++)
            pre[j] = *(const float4*)(vbase + (size_t)(32 + srow + j * 4) * DD + sc4);
    }
    __syncthreads();

#pragma unroll 1
    for (int cc = 0; cc < 8; cc++) {
        const uint32_t* vu = (const uint32_t*)(vt + (cc & 1) * RBUF);
        if (cc + 1 < 8) {
            float* nxt = vt + ((cc + 1) & 1) * RBUF;
#pragma unroll
            for (int j = 0; j < 8; j++) {
                uint32_t* dst = (uint32_t*)&nxt[(srow + j * 4) * PV + sc4];
                dst[0] = f2tf(pre[j].x); dst[1] = f2tf(pre[j].y);
                dst[2] = f2tf(pre[j].z); dst[3] = f2tf(pre[j].w);
            }
        }
        if (cc + 2 < 8) {
            int tc = (cc + 2) * 32;
#pragma unroll
            for (int j = 0; j < 8; j++)
                pre[j] = *(const float4*)(vbase + (size_t)(tc + srow + j * 4) * DD + sc4);
        }
        int tc = cc * 32;
#pragma unroll
        for (int k8 = 0; k8 < 4; k8++) {
            uint32_t a[MT][4], b[4][2];
            int kg = tc + k8 * 8 + qk;
            int kl = k8 * 8 + qk;
#pragma unroll
            for (int mt = 0; mt < MT; mt++) {
                int m0 = mt * 16 + qrow;
                a[mt][0] = au[m0 * PQ + kg];
                a[mt][1] = au[(m0 + 8) * PQ + kg];
                a[mt][2] = au[m0 * PQ + kg + 4];
                a[mt][3] = au[(m0 + 8) * PQ + kg + 4];
            }
#pragma unroll
            for (int nt = 0; nt < 4; nt++) {
                int d = wd + nt * 8 + qrow;
                b[nt][0] = vu[kl * PV + d];
                b[nt][1] = vu[(kl + 4) * PV + d];
            }
#pragma unroll
            for (int mt = 0; mt < MT; mt++)
#pragma unroll
                for (int nt = 0; nt < 4; nt++)
                    mma_tf32(c[mt][nt], a[mt], b[nt]);
        }
        __syncthreads();
    }
}

template<int MT, int NRS>
__device__ __forceinline__ void upd_atomics(float c[MT][4][4], float* __restrict__ gacc,
                                            int slot_base, int t) {
    int lane = t & 31, wid = t >> 5;
    int qrow = lane >> 2, qk = lane & 3;
    int wd = wid * 32;
#pragma unroll
    for (int mt = 0; mt < MT; mt++)
#pragma unroll
        for (int nt = 0; nt < 4; nt++) {
            int d  = wd + nt * 8 + 2 * qk;
            int s0 = mt * 16 + qrow;
            atomicAdd(&gacc[(size_t)(slot_base + s0) * DD + d],     c[mt][nt][0]);
            atomicAdd(&gacc[(size_t)(slot_base + s0) * DD + d + 1], c[mt][nt][1]);
            if (s0 + 8 < NRS) {
                atomicAdd(&gacc[(size_t)(slot_base + s0 + 8) * DD + d],     c[mt][nt][2]);
                atomicAdd(&gacc[(size_t)(slot_base + s0 + 8) * DD + d + 1], c[mt][nt][3]);
            }
        }
}

// ---------------- 6) fused sem (mma) ----------------
__global__ void __launch_bounds__(256) sem_fused_kernel(int write_dots) {
    extern __shared__ float smem[];
    float* qs   = smem;                 // 16*PQ
    float* reg2 = smem + 16 * PQ;       // 2*RBUF
    const int PD = 17;

    int b  = blockIdx.y;
    int n0 = blockIdx.x * 256;
    int t  = threadIdx.x;
    int n  = n0 + t;

    for (int idx = t; idx < NSL * DD; idx += 256) {
        int r = idx >> 8, cc = idx & 255;
        ((uint32_t*)qs)[r * PQ + cc] = f2tf(g_sem_q[(size_t)b * NSL * DD + idx]);
    }
    for (int idx = t; idx < 8 * DD; idx += 256) {
        int r = idx >> 8, cc = idx & 255;
        qs[(NSL + r) * PQ + cc] = 0.f;
    }

    float c[1][4][4];
    dots_phase<1>(g_k + ((size_t)b * NN + n0) * DD, qs, reg2, c, t);

    store_dots<1, PD>(c, reg2, t);
    __syncthreads();

    float dv[NSL], e[NSL];
    float mx = -1e30f;
#pragma unroll
    for (int i = 0; i < NSL; i++) { dv[i] = reg2[t * PD + i]; mx = fmaxf(mx, dv[i]); }
    float ssum = 0.f;
#pragma unroll
    for (int i = 0; i < NSL; i++) { e[i] = expf(dv[i] - mx); ssum += e[i]; }
    float inv = 1.0f / ssum;

    size_t base = (size_t)b * NSL * NN + n;
    int l = t & 31;
    float at[NSL];
#pragma unroll
    for (int i = 0; i < NSL; i++) {
        at[i] = e[i] * inv + EPS_F;
        if (write_dots) g_sem_dots[base + (size_t)i * NN] = dv[i];
        float sv = warp_sum(at[i]);
        if (l == 0) atomicAdd(&g_sem_rowsum[b * NSL + i], sv);
    }

    __syncthreads();
#pragma unroll
    for (int i = 0; i < NSL; i++)
        ((uint32_t*)qs)[i * PQ + t] = f2tf(at[i]);
#pragma unroll
    for (int i = NSL; i < 16; i++)
        qs[i * PQ + t] = 0.f;
    __syncthreads();

    float c2[1][4][4];
    upd_phase<1>(g_v + ((size_t)b * NN + n0) * DD, qs, reg2, c2, t);
    upd_atomics<1, NSL>(c2, g_sem_acc, b * NSL, t);
}

// ---------------- 7) fused inst (mma) ----------------
__global__ void __launch_bounds__(256) inst_fused_kernel(int write_dots) {
    extern __shared__ float smem[];
    float* qs   = smem;                 // 32*PQ
    float* reg2 = smem + 32 * PQ;       // 2*RBUF
    const int PD = 33;

    int b  = blockIdx.y;
    int n0 = blockIdx.x * 256;
    int t  = threadIdx.x;
    int n  = n0 + t;

    for (int idx = t; idx < 32 * DD; idx += 256) {
        int r = idx >> 8, cc = idx & 255;
        ((uint32_t*)qs)[r * PQ + cc] = f2tf(g_inst_q[(size_t)b * 32 * DD + idx]);
    }

    float c[2][4][4];
    dots_phase<2>(g_k + ((size_t)b * NN + n0) * DD, qs, reg2, c, t);

    store_dots<2, PD>(c, reg2, t);
    __syncthreads();

    float wv[NSL];
    {
        size_t sbase = (size_t)b * NSL * NN + n;
        float sdv[NSL];
        float smx = -1e30f;
#pragma unroll
        for (int i = 0; i < NSL; i++) { sdv[i] = g_sem_dots[sbase + (size_t)i * NN]; smx = fmaxf(smx, sdv[i]); }
        float ss = 0.f;
#pragma unroll
        for (int i = 0; i < NSL; i++) { sdv[i] = expf(sdv[i] - smx); ss += sdv[i]; }
        float sinv = 1.0f / ss;
#pragma unroll
        for (int i = 0; i < NSL; i++) wv[i] = sdv[i] * sinv;
    }

    size_t dbase = (size_t)b * 32 * NN + n;
    int l = t & 31;
    float at[32];
#pragma unroll
    for (int s = 0; s < 8; s++) {
        float dv[NPI], e[NPI];
        float mx = -1e30f;
#pragma unroll
        for (int p = 0; p < NPI; p++) { dv[p] = reg2[t * PD + s * 4 + p]; mx = fmaxf(mx, dv[p]); }
        float ssum = 0.f;
#pragma unroll
        for (int p = 0; p < NPI; p++) { e[p] = expf(dv[p] - mx); ssum += e[p]; }
        float invs = 1.0f / ssum;
#pragma unroll
        for (int p = 0; p < NPI; p++) {
            int sp = s * 4 + p;
            at[sp] = (e[p] * invs + EPS_F) * wv[s];
            if (write_dots) g_inst_dots[dbase + (size_t)sp * NN] = dv[p];
            float sv = warp_sum(at[sp]);
            if (l == 0) atomicAdd(&g_inst_rowsum[b * 32 + sp], sv);
        }
    }

    __syncthreads();
#pragma unroll
    for (int i = 0; i < 32; i++)
        ((uint32_t*)qs)[i * PQ + t] = f2tf(at[i]);
    __syncthreads();

    float c2[2][4][4];
    upd_phase<2>(g_v + ((size_t)b * NN + n0) * DD, qs, reg2, c2, t);
    upd_atomics<2, 32>(c2, g_inst_acc, b * 32, t);
}

// ---------------- 8) assemble output ----------------
__global__ void __launch_bounds__(256) write_out_kernel(float* __restrict__ out) {
    size_t idx = (size_t)blockIdx.x * 256 + threadIdx.x;
    const size_t A1 = 32768;
    const size_t A2 = 557056;
    const size_t A3 = 688128;
    const size_t A4 = 2785280;
    if (idx >= A4) return;
    float v;
    if (idx < A1)      v = g_sem_slots[idx];
    else if (idx < A2) v = g_sem_dots[idx - A1];
    else if (idx < A3) v = g_inst_slots[idx - A2];
    else               v = g_inst_dots[idx - A3];
    out[idx] = v;
}

// ---------------- launch ----------------
extern "C" void kernel_launch(void* const* d_in, const int* in_sizes, int n_in,
                              void* d_out, int out_size) {
    (void)in_sizes; (void)n_in; (void)out_size;
    const float* inputs      = (const float*)d_in[0];
    const float* noise       = (const float*)d_in[3];
    const float* ln_in_g     = (const float*)d_in[4];
    const float* ln_in_b     = (const float*)d_in[5];
    const float* ln_s_g      = (const float*)d_in[6];
    const float* ln_s_b      = (const float*)d_in[7];
    const float* ln_ff_g     = (const float*)d_in[8];
    const float* ln_ff_b     = (const float*)d_in[9];
    const float* slots_mu    = (const float*)d_in[10];
    const float* slots_sigma = (const float*)d_in[11];
    const float* Wq          = (const float*)d_in[12];
    const float* bq          = (const float*)d_in[13];
    const float* Wk          = (const float*)d_in[14];
    const float* bk          = (const float*)d_in[15];
    const float* Wv          = (const float*)d_in[16];
    const float* bv          = (const float*)d_in[17];
    const float* W1          = (const float*)d_in[18];
    const float* b1          = (const float*)d_in[19];
    const float* W2          = (const float*)d_in[20];
    const float* b2          = (const float*)d_in[21];
    float* out = (float*)d_out;

    const int sem_smem  = (16 * PQ + 2 * RBUF) * 4;   // 90,368 B
    const int inst_smem = (32 * PQ + 2 * RBUF) * 4;   // 107,008 B
    const int gemm_smem = 2 * GBUF * 4;               // 73,728 B
    static int attr_done = 0;
    if (!attr_done) {
        cudaFuncSetAttribute(sem_fused_kernel,  cudaFuncAttributeMaxDynamicSharedMemorySize, sem_smem);
        cudaFuncSetAttribute(inst_fused_kernel, cudaFuncAttributeMaxDynamicSharedMemorySize, inst_smem);
        cudaFuncSetAttribute(gemm_tf32_kernel,  cudaFuncAttributeMaxDynamicSharedMemorySize, gemm_smem);
        attr_done = 1;
    }

    prep_b_kernel<<<128, 256>>>(Wk, Wv);
    ln_input_kernel<<<BB * NN, 256>>>(inputs, ln_in_g, ln_in_b);

    dim3 gemm_grid(4, 512);
    gemm_tf32_kernel<<<gemm_grid, 256, gemm_smem>>>(bk, bv);

    sem_init_kernel<<<BB * NSL, 256>>>(slots_mu);

    dim3 bn_grid(16, 16);
    const int SEM_BLKS  = BB * NSL / 4;        // 32
    const int INST_BLKS = BB * NSL * NPI / 4;  // 128

    mlpq_kernel<false, true><<<SEM_BLKS, 256>>>(0, ln_ff_g, ln_ff_b, W1, b1, W2, b2,
                                                ln_s_g, ln_s_b, Wq, bq);
    for (int it = 0; it < 3; it++) {
        sem_fused_kernel<<<bn_grid, 256, sem_smem>>>(it == 2 ? 1 : 0);
        if (it < 2)
            mlpq_kernel<true, true><<<SEM_BLKS, 256>>>(0, ln_ff_g, ln_ff_b, W1, b1, W2, b2,
                                                       ln_s_g, ln_s_b, Wq, bq);
        else
            mlpq_kernel<true, false><<<SEM_BLKS, 256>>>(0, ln_ff_g, ln_ff_b, W1, b1, W2, b2,
                                                        ln_s_g, ln_s_b, Wq, bq);
    }

    inst_init_kernel<<<BB * NSL * NPI, 256>>>(slots_mu, slots_sigma, noise);

    mlpq_kernel<false, true><<<INST_BLKS, 256>>>(1, ln_ff_g, ln_ff_b, W1, b1, W2, b2,
                                                 ln_s_g, ln_s_b, Wq, bq);
    for (int it = 0; it < 3; it++) {
        inst_fused_kernel<<<bn_grid, 256, inst_smem>>>(it == 2 ? 1 : 0);
        if (it < 2)
            mlpq_kernel<true, true><<<INST_BLKS, 256>>>(1, ln_ff_g, ln_ff_b, W1, b1, W2, b2,
                                                        ln_s_g, ln_s_b, Wq, bq);
        else
            mlpq_kernel<true, false><<<INST_BLKS, 256>>>(1, ln_ff_g, ln_ff_b, W1, b1, W2, b2,
                                                         ln_s_g, ln_s_b, Wq, bq);
    }

    write_out_kernel<<<10880, 256>>>(out);
}